// round 11
// baseline (speedup 1.0000x reference)
#include <cuda_runtime.h>
#include <cuda_fp16.h>
#include <math.h>
#include <stdint.h>

// Problem constants
#define LNUM 4
#define DM   1024
#define HN   16
#define DH   64
#define FFN  4096
#define VN   8192
#define BN   4
#define QN   512
#define MN   512
#define EN   512
#define KLEN 1024   // M + Q

// ---------------- scratch (device globals; no allocation) ----------------
__device__ float  g_x   [BN*QN*DM];         // residual stream (full fp32)
__device__ float  g_tmp [BN*QN*DM];
__device__ float  g_bd  [BN*HN*QN*KLEN];
// half activation buffers
__device__ __half g_hxh  [BN*QN*DM];
__device__ __half g_hmem [BN*KLEN*DM];
__device__ __half g_hqkv [BN*KLEN*3072];
__device__ __half g_hcakv[BN*EN*8192];
__device__ __half g_hr4  [KLEN*4096];
__device__ __half g_hatt [BN*QN*DM];
__device__ __half g_hq   [BN*QN*DM];
__device__ __half g_hff  [BN*QN*FFN];
__device__ __half g_hremb[KLEN*DM];
__device__ __half g_henc [BN*EN*DM];
// transposed half weights (B^T, [n][k] row-major), built per call
__device__ __half g_wqkv [LNUM*3072*DM];
__device__ __half g_wcakv[8192*DM];
__device__ __half g_wr4  [4096*DM];
__device__ __half g_wsafc[LNUM*DM*DM];
__device__ __half g_wcafc[LNUM*DM*DM];
__device__ __half g_wcaq [LNUM*DM*DM];
__device__ __half g_wff1 [LNUM*FFN*DM];
__device__ __half g_wff2 [LNUM*DM*FFN];
__device__ __half g_wout [VN*DM];

// ---------------- helpers ----------------
__device__ __forceinline__ unsigned f2tf(float x) {
    unsigned u; asm("cvt.rna.tf32.f32 %0, %1;" : "=r"(u) : "f"(x)); return u;
}

#define MMA_TF32(C, A, B0, B1)                                                \
    asm volatile(                                                             \
        "mma.sync.aligned.m16n8k8.row.col.f32.tf32.tf32.f32 "                 \
        "{%0,%1,%2,%3}, {%4,%5,%6,%7}, {%8,%9}, {%0,%1,%2,%3};"               \
        : "+f"((C)[0]), "+f"((C)[1]), "+f"((C)[2]), "+f"((C)[3])              \
        : "r"((A)[0]), "r"((A)[1]), "r"((A)[2]), "r"((A)[3]),                 \
          "r"(B0), "r"(B1))

#define MMA_F16(C, A0, A1, A2, A3, B0, B1)                                    \
    asm volatile(                                                             \
        "mma.sync.aligned.m16n8k16.row.col.f32.f16.f16.f32 "                  \
        "{%0,%1,%2,%3}, {%4,%5,%6,%7}, {%8,%9}, {%0,%1,%2,%3};"               \
        : "+f"((C)[0]), "+f"((C)[1]), "+f"((C)[2]), "+f"((C)[3])              \
        : "r"(A0), "r"(A1), "r"(A2), "r"(A3), "r"(B0), "r"(B1))

__device__ __forceinline__ void cp16(uint32_t dst, const void* src) {
    asm volatile("cp.async.cg.shared.global [%0], [%1], 16;\n" :: "r"(dst), "l"(src));
}
#define CP_COMMIT()  asm volatile("cp.async.commit_group;\n" ::)

__device__ __forceinline__ uint32_t smem_u32(const void* p) {
    uint32_t a;
    asm("{ .reg .u64 t; cvta.to.shared.u64 t, %1; cvt.u32.u64 %0, t; }"
        : "=r"(a) : "l"(p));
    return a;
}
__device__ __forceinline__ uint32_t packh2(float a, float b) {
    __half2 h = __floats2half2_rn(a, b);
    return *(uint32_t*)&h;
}

// ---------------- elementwise kernels ----------------
__global__ void half_copy(const float* __restrict__ src,
                          __half* __restrict__ dst, int n4) {
    int i = blockIdx.x * blockDim.x + threadIdx.x;
    if (i >= n4) return;
    float4 v = ((const float4*)src)[i];
    ((__half2*)dst)[2*i]   = __floats2half2_rn(v.x, v.y);
    ((__half2*)dst)[2*i+1] = __floats2half2_rn(v.z, v.w);
}

// transpose + half: src [R, C] fp32 row-major -> dst [C, R] half row-major
__global__ void trans_half(const float* __restrict__ src, __half* __restrict__ dst,
                           int R, int C, size_t sbs, size_t dbs) {
    __shared__ float t[32][33];
    const float* s = src + (size_t)blockIdx.z * sbs;
    __half*      d = dst + (size_t)blockIdx.z * dbs;
    int c0 = blockIdx.x * 32, r0 = blockIdx.y * 32;
    int tx = threadIdx.x, ty = threadIdx.y;
    #pragma unroll
    for (int i = 0; i < 4; i++)
        t[ty + 8*i][tx] = s[(size_t)(r0 + ty + 8*i) * C + c0 + tx];
    __syncthreads();
    #pragma unroll
    for (int i = 0; i < 4; i++)
        d[(size_t)(c0 + ty + 8*i) * R + r0 + tx] = __float2half_rn(t[tx][ty + 8*i]);
}

__global__ void embed_kernel(const int* __restrict__ ids,
                             const float* __restrict__ emb,
                             float* __restrict__ x) {
    int idx = blockIdx.x * blockDim.x + threadIdx.x;
    if (idx >= BN*QN*DM) return;
    int row = idx / DM;
    int d   = idx - row * DM;
    int tok = ids[row];
    x[idx] = emb[tok * DM + d] * 32.0f;
}

__global__ void remb_kernel(__half* __restrict__ remb) {
    int idx = blockIdx.x * blockDim.x + threadIdx.x;
    if (idx >= KLEN*DM) return;
    int p = idx / DM;
    int d = idx - p * DM;
    float pos = (float)(KLEN - 1 - p);
    int k = (d < DM/2) ? d : d - DM/2;
    float invf = powf(10000.0f, -(float)k / (float)(DM/2));
    float a = pos * invf;
    remb[idx] = __float2half_rn((d < DM/2) ? sinf(a) : cosf(a));
}

__global__ void concat_kernel(const float* __restrict__ mems_l,
                              const float* __restrict__ x,
                              __half* __restrict__ mem) {
    int idx = blockIdx.x * blockDim.x + threadIdx.x;
    if (idx >= BN*KLEN*DM) return;
    int d   = idx % DM;
    int rem = idx / DM;
    int j   = rem % KLEN;
    int b   = rem / KLEN;
    float val;
    if (j < MN) val = mems_l[(b*MN + j)*DM + d];
    else        val = x[(b*QN + (j - MN))*DM + d];
    mem[idx] = __float2half_rn(val);
}

// ---------------- fp16 tensor-core GEMM, 4-stage cp.async, 2 CTAs/SM -------
// C[N,K] = A[N,D] @ W[D,K]; Bt = W^T as half [K, D] row-major.
// NT = 8 -> 128x128 tile; NT = 4 -> 128x64 tile (for small grids).
#define STG    4
#define ROWU   12                      // uints per smem row (8 data + 4 pad)
#define MM_SMEM8 (STG*(128*ROWU + 128*ROWU)*4)
#define MM_SMEM4 (STG*(128*ROWU +  64*ROWU)*4)

template<bool GELU, bool HOUT, int NT>
__global__ __launch_bounds__(256, 2)
void mm_h(const __half* __restrict__ A, const __half* __restrict__ Bt,
          const float* __restrict__ bias, void* __restrict__ Cout,
          int N, int D, int K) {
    constexpr int TAU = 128*ROWU;
    constexpr int TBU = NT*16*ROWU;
    constexpr int SU  = TAU + TBU;
    extern __shared__ uint32_t smu[];
    const uint32_t sb = smem_u32(smu);

    const int tid  = threadIdx.x;
    const int row0 = blockIdx.y * 128, col0 = blockIdx.x * (NT*16);
    const int lane = tid & 31, wid = tid >> 5;
    const int grp  = lane >> 2, t4 = lane & 3;
    const int wm   = (wid & 3) * 32, wn = (wid >> 2) * (NT*8);

    const int lrow = tid >> 1;
    const int lseg = tid & 1;
    const __half* Ag = A + (size_t)(row0 + lrow) * D + lseg * 8;
    const uint32_t dstA = sb + (lrow*ROWU + lseg*4) * 4;

    const bool doB = (NT == 8) || (tid < 128);
    const int brow = (NT == 8) ? lrow : (tid >> 1);
    const int bseg = (NT == 8) ? lseg : (tid & 1);
    const __half* Bg = Bt + (size_t)(col0 + brow) * D + bseg * 8;
    const uint32_t dstB = sb + (TAU + brow*ROWU + bseg*4) * 4;

    const int KT = D >> 4;

    float c[2][NT][4];
    #pragma unroll
    for (int i = 0; i < 2; i++)
        #pragma unroll
        for (int j = 0; j < NT; j++)
            #pragma unroll
            for (int t = 0; t < 4; t++) c[i][j][t] = 0.0f;

    #pragma unroll
    for (int s = 0; s < STG-1; s++) {
        cp16(dstA + s*SU*4, Ag + (size_t)s*16);
        if (doB) cp16(dstB + s*SU*4, Bg + (size_t)s*16);
        CP_COMMIT();
    }

    for (int kt = 0; kt < KT; kt++) {
        asm volatile("cp.async.wait_group 2;\n" ::);
        __syncthreads();
        const int st = kt & (STG-1);
        const uint32_t* AsU = smu + st*SU;
        const uint32_t* BsU = AsU + TAU;

        uint32_t af[2][4], bf[NT][2];
        #pragma unroll
        for (int mt = 0; mt < 2; mt++) {
            const int m = wm + mt*16 + grp;
            af[mt][0] = AsU[(m  )*ROWU + t4    ];
            af[mt][1] = AsU[(m+8)*ROWU + t4    ];
            af[mt][2] = AsU[(m  )*ROWU + t4 + 4];
            af[mt][3] = AsU[(m+8)*ROWU + t4 + 4];
        }
        #pragma unroll
        for (int nt = 0; nt < NT; nt++) {
            const int n = wn + nt*8 + grp;
            bf[nt][0] = BsU[n*ROWU + t4    ];
            bf[nt][1] = BsU[n*ROWU + t4 + 4];
        }

        const int kn = kt + STG - 1;
        if (kn < KT) {
            const int sn = kn & (STG-1);
            cp16(dstA + sn*SU*4, Ag + (size_t)kn*16);
            if (doB) cp16(dstB + sn*SU*4, Bg + (size_t)kn*16);
        }
        CP_COMMIT();

        #pragma unroll
        for (int mt = 0; mt < 2; mt++)
            #pragma unroll
            for (int nt = 0; nt < NT; nt++)
                MMA_F16(c[mt][nt], af[mt][0], af[mt][1], af[mt][2], af[mt][3],
                        bf[nt][0], bf[nt][1]);
    }

    #pragma unroll
    for (int mt = 0; mt < 2; mt++)
        #pragma unroll
        for (int nt = 0; nt < NT; nt++) {
            int r  = row0 + wm + mt*16 + grp;
            int cc = col0 + wn + nt*8 + t4*2;
            #pragma unroll
            for (int half = 0; half < 2; half++) {
                int rr = r + half*8;
                float v0 = c[mt][nt][half*2 + 0];
                float v1 = c[mt][nt][half*2 + 1];
                if (bias) { v0 += bias[cc]; v1 += bias[cc+1]; }
                if (GELU) {
                    v0 = 0.5f*v0*(1.0f + erff(v0*0.70710678118654752f));
                    v1 = 0.5f*v1*(1.0f + erff(v1*0.70710678118654752f));
                }
                if (HOUT) {
                    __half* Ch = (__half*)Cout;
                    *(__half2*)&Ch[(size_t)rr*K + cc] = __floats2half2_rn(v0, v1);
                } else {
                    float* Cf = (float*)Cout;
                    *(float2*)&Cf[(size_t)rr*K + cc] = make_float2(v0, v1);
                }
            }
        }
}

// ---------------- BD_raw via fp16 tensor cores ----------------
// bdout[b,h,i,t] = sum_d (q[i,h,d] + vvec[h,d]) * r[t,h,d]
#define RS_WSTR 36   // words per R row (32 data + 4 pad) -> banks 4*grp+t4
__global__ __launch_bounds__(256)
void bd_mma(const __half* __restrict__ q, int qrs, size_t qbs,
            const __half* __restrict__ r, int rrs,
            const float* __restrict__ vvec, float* __restrict__ bdout) {
    __shared__ uint32_t RsU[64*RS_WSTR];
    const int t0 = blockIdx.x * 64;
    const int i0 = blockIdx.y * 128;
    const int h = blockIdx.z & (HN-1), b = blockIdx.z >> 4;
    const int tid = threadIdx.x;
    const int lane = tid & 31, wid = tid >> 5;
    const int grp = lane >> 2, t4 = lane & 3;
    const int i_r0 = i0 + wid*16 + grp, i_r1 = i_r0 + 8;

    uint32_t qf[4][4];
    {
        const __half* qp0 = q + (size_t)b*qbs + (size_t)i_r0*qrs + h*DH;
        const __half* qp1 = q + (size_t)b*qbs + (size_t)i_r1*qrs + h*DH;
        const float* up  = vvec + h*DH;
        #pragma unroll
        for (int ks = 0; ks < 4; ks++) {
            int k0 = 16*ks + 2*t4;
            float ua = up[k0], ub = up[k0+1], uc = up[k0+8], ud = up[k0+9];
            qf[ks][0] = packh2(__half2float(qp0[k0])   + ua, __half2float(qp0[k0+1]) + ub);
            qf[ks][1] = packh2(__half2float(qp1[k0])   + ua, __half2float(qp1[k0+1]) + ub);
            qf[ks][2] = packh2(__half2float(qp0[k0+8]) + uc, __half2float(qp0[k0+9]) + ud);
            qf[ks][3] = packh2(__half2float(qp1[k0+8]) + uc, __half2float(qp1[k0+9]) + ud);
        }
    }
    #pragma unroll
    for (int t = 0; t < 2; t++) {
        int idx = tid + 256*t;
        int row = idx >> 3, c8 = (idx & 7) * 8;
        uint4 rv = *(const uint4*)&r[(size_t)(t0 + row)*rrs + h*DH + c8];
        *(uint4*)&RsU[row*RS_WSTR + (idx & 7)*4] = rv;
    }
    __syncthreads();

    float s[8][4];
    #pragma unroll
    for (int nt = 0; nt < 8; nt++)
        #pragma unroll
        for (int e = 0; e < 4; e++) s[nt][e] = 0.0f;

    #pragma unroll
    for (int ks = 0; ks < 4; ks++)
        #pragma unroll
        for (int nt = 0; nt < 8; nt++) {
            uint32_t b0 = RsU[(nt*8+grp)*RS_WSTR + t4 + 8*ks];
            uint32_t b1 = RsU[(nt*8+grp)*RS_WSTR + t4 + 4 + 8*ks];
            MMA_F16(s[nt], qf[ks][0], qf[ks][1], qf[ks][2], qf[ks][3], b0, b1);
        }

    float* o0 = bdout + (((size_t)(b*HN + h))*QN + i_r0)*KLEN + t0;
    float* o1 = bdout + (((size_t)(b*HN + h))*QN + i_r1)*KLEN + t0;
    #pragma unroll
    for (int nt = 0; nt < 8; nt++) {
        int cc = nt*8 + 2*t4;
        *(float2*)&o0[cc] = make_float2(s[nt][0], s[nt][1]);
        *(float2*)&o1[cc] = make_float2(s[nt][2], s[nt][3]);
    }
}

// ---------------- MMA flash attention: fp16 QK^T, tf32 PV ----------------
#define KS_WSTR 36
#define VS_STRIDE 72
#define PS_STRIDE 68
#define FLASH_SMEM ((64*KS_WSTR + 64*VS_STRIDE + 128*PS_STRIDE) * 4)

__global__ __launch_bounds__(256)
void flashmma(const __half* __restrict__ q, int qrs, size_t qbs,
              const __half* __restrict__ k, const __half* __restrict__ v,
              int kvrs, size_t kvbs,
              const float* __restrict__ bd, const float* __restrict__ uvec,
              __half* __restrict__ out, int klen, int useMask) {
    extern __shared__ uint32_t smu[];
    uint32_t* KsU = smu;
    float* Vs = (float*)(smu + 64*KS_WSTR);
    float* Ps = Vs + 64*VS_STRIDE;

    const int i0 = blockIdx.x * 128;
    const int h = blockIdx.y, b = blockIdx.z;
    const int tid = threadIdx.x;
    const int lane = tid & 31, wid = tid >> 5;
    const int grp = lane >> 2, t4 = lane & 3;
    const int r0 = wid*16 + grp, r1 = r0 + 8;
    const int i_r0 = i0 + r0, i_r1 = i0 + r1;

    uint32_t qf[4][4];
    {
        const __half* qp0 = q + (size_t)b*qbs + (size_t)i_r0*qrs + h*DH;
        const __half* qp1 = q + (size_t)b*qbs + (size_t)i_r1*qrs + h*DH;
        #pragma unroll
        for (int ks = 0; ks < 4; ks++) {
            int k0 = 16*ks + 2*t4;
            float ua = uvec ? uvec[h*DH + k0]   : 0.0f;
            float ub = uvec ? uvec[h*DH + k0+1] : 0.0f;
            float uc = uvec ? uvec[h*DH + k0+8] : 0.0f;
            float ud = uvec ? uvec[h*DH + k0+9] : 0.0f;
            qf[ks][0] = packh2(__half2float(qp0[k0])   + ua, __half2float(qp0[k0+1]) + ub);
            qf[ks][1] = packh2(__half2float(qp1[k0])   + ua, __half2float(qp1[k0+1]) + ub);
            qf[ks][2] = packh2(__half2float(qp0[k0+8]) + uc, __half2float(qp0[k0+9]) + ud);
            qf[ks][3] = packh2(__half2float(qp1[k0+8]) + uc, __half2float(qp1[k0+9]) + ud);
        }
    }

    float m0 = -INFINITY, m1 = -INFINITY, l0 = 0.0f, l1 = 0.0f;
    float o[8][4];
    #pragma unroll
    for (int nt = 0; nt < 8; nt++)
        #pragma unroll
        for (int e = 0; e < 4; e++) o[nt][e] = 0.0f;

    const float* bdr0 = bd ? bd + (((size_t)(b*HN + h))*QN + i_r0)*KLEN : (const float*)0;
    const float* bdr1 = bd ? bd + (((size_t)(b*HN + h))*QN + i_r1)*KLEN : (const float*)0;

    int lastj = klen - 1;
    if (useMask) { int lm = i0 + 127 + MN; if (lm < lastj) lastj = lm; }

    for (int j0 = 0; j0 <= lastj; j0 += 64) {
        __syncthreads();
        #pragma unroll
        for (int t = 0; t < 2; t++) {
            int idx = tid + 256*t;
            int row = idx >> 3, c8 = (idx & 7) * 8;
            size_t gb = (size_t)b*kvbs + (size_t)(j0 + row)*kvrs + h*DH + c8;
            uint4 kv = *(const uint4*)&k[gb];
            uint4 vv = *(const uint4*)&v[gb];
            *(uint4*)&KsU[row*KS_WSTR + (idx & 7)*4] = kv;
            float* vd = Vs + row*VS_STRIDE + c8;
            float2 f0 = __half22float2(*(__half2*)&vv.x);
            float2 f1 = __half22float2(*((__half2*)&vv.x + 1));
            float2 f2 = __half22float2(*(__half2*)&vv.z);
            float2 f3 = __half22float2(*((__half2*)&vv.z + 1));
            vd[0]=f0.x; vd[1]=f0.y; vd[2]=f1.x; vd[3]=f1.y;
            vd[4]=f2.x; vd[5]=f2.y; vd[6]=f3.x; vd[7]=f3.y;
        }
        __syncthreads();

        float bdv[8][4];
        if (bd) {
            #pragma unroll
            for (int nt = 0; nt < 8; nt++) {
                int jA = j0 + nt*8 + 2*t4;
                int jr0 = jA - i_r0 + (QN-1);
                int jr1 = jA - i_r1 + (QN-1);
                jr0 = max(0, min(KLEN-2, jr0));
                jr1 = max(0, min(KLEN-2, jr1));
                bdv[nt][0] = bdr0[jr0];   bdv[nt][1] = bdr0[jr0+1];
                bdv[nt][2] = bdr1[jr1];   bdv[nt][3] = bdr1[jr1+1];
            }
        }

        // S = Q @ K^T  (fp16)
        float s[8][4];
        #pragma unroll
        for (int nt = 0; nt < 8; nt++)
            #pragma unroll
            for (int e = 0; e < 4; e++) s[nt][e] = 0.0f;
        #pragma unroll
        for (int ks = 0; ks < 4; ks++)
            #pragma unroll
            for (int nt = 0; nt < 8; nt++) {
                uint32_t b0 = KsU[(nt*8+grp)*KS_WSTR + t4 + 8*ks];
                uint32_t b1 = KsU[(nt*8+grp)*KS_WSTR + t4 + 4 + 8*ks];
                MMA_F16(s[nt], qf[ks][0], qf[ks][1], qf[ks][2], qf[ks][3], b0, b1);
            }

        float mc0 = -INFINITY, mc1 = -INFINITY;
        #pragma unroll
        for (int nt = 0; nt < 8; nt++) {
            int jA = j0 + nt*8 + 2*t4;
            int jB = jA + 1;
            float v0 = s[nt][0], v1 = s[nt][1], v2 = s[nt][2], v3 = s[nt][3];
            if (bd) { v0 += bdv[nt][0]; v1 += bdv[nt][1]; v2 += bdv[nt][2]; v3 += bdv[nt][3]; }
            v0 *= 0.125f; v1 *= 0.125f; v2 *= 0.125f; v3 *= 0.125f;
            if (useMask) {
                if (jA > i_r0 + MN) v0 = -INFINITY;
                if (jB > i_r0 + MN) v1 = -INFINITY;
                if (jA > i_r1 + MN) v2 = -INFINITY;
                if (jB > i_r1 + MN) v3 = -INFINITY;
            }
            s[nt][0]=v0; s[nt][1]=v1; s[nt][2]=v2; s[nt][3]=v3;
            mc0 = fmaxf(mc0, fmaxf(v0, v1));
            mc1 = fmaxf(mc1, fmaxf(v2, v3));
        }
        mc0 = fmaxf(mc0, __shfl_xor_sync(0xffffffffu, mc0, 1));
        mc0 = fmaxf(mc0, __shfl_xor_sync(0xffffffffu, mc0, 2));
        mc1 = fmaxf(mc1, __shfl_xor_sync(0xffffffffu, mc1, 1));
        mc1 = fmaxf(mc1, __shfl_xor_sync(0xffffffffu, mc1, 2));

        float nm0 = fmaxf(m0, mc0), nm1 = fmaxf(m1, mc1);
        float corr0 = __expf(m0 - nm0), corr1 = __expf(m1 - nm1);
        float ps0 = 0.0f, ps1 = 0.0f;
        #pragma unroll
        for (int nt = 0; nt < 8; nt++) {
            float p0 = __expf(s[nt][0] - nm0);
            float p1 = __expf(s[nt][1] - nm0);
            float p2 = __expf(s[nt][2] - nm1);
            float p3 = __expf(s[nt][3] - nm1);
            ps0 += p0 + p1; ps1 += p2 + p3;
            int cc = nt*8 + 2*t4;
            Ps[r0*PS_STRIDE + cc]     = __uint_as_float(f2tf(p0));
            Ps[r0*PS_STRIDE + cc + 1] = __uint_as_float(f2tf(p1));
            Ps[r1*PS_STRIDE + cc]     = __uint_as_float(f2tf(p2));
            Ps[r1*PS_STRIDE + cc + 1] = __uint_as_float(f2tf(p3));
        }
        ps0 += __shfl_xor_sync(0xffffffffu, ps0, 1);
        ps0 += __shfl_xor_sync(0xffffffffu, ps0, 2);
        ps1 += __shfl_xor_sync(0xffffffffu, ps1, 1);
        ps1 += __shfl_xor_sync(0xffffffffu, ps1, 2);
        l0 = l0 * corr0 + ps0;  m0 = nm0;
        l1 = l1 * corr1 + ps1;  m1 = nm1;
        #pragma unroll
        for (int nt = 0; nt < 8; nt++) {
            o[nt][0] *= corr0; o[nt][1] *= corr0;
            o[nt][2] *= corr1; o[nt][3] *= corr1;
        }
        __syncwarp();

        // O += P @ V  (tf32)
        #pragma unroll
        for (int ks = 0; ks < 8; ks++) {
            unsigned a[4];
            a[0] = __float_as_uint(Ps[r0*PS_STRIDE + ks*8 + t4]);
            a[1] = __float_as_uint(Ps[r1*PS_STRIDE + ks*8 + t4]);
            a[2] = __float_as_uint(Ps[r0*PS_STRIDE + ks*8 + t4 + 4]);
            a[3] = __float_as_uint(Ps[r1*PS_STRIDE + ks*8 + t4 + 4]);
            #pragma unroll
            for (int nt = 0; nt < 8; nt++) {
                unsigned b0 = __float_as_uint(Vs[(ks*8+t4)*VS_STRIDE + nt*8 + grp]);
                unsigned b1 = __float_as_uint(Vs[(ks*8+t4+4)*VS_STRIDE + nt*8 + grp]);
                MMA_TF32(o[nt], a, b0, b1);
            }
        }
    }

    const float inv0 = 1.0f / l0, inv1 = 1.0f / l1;
    __half* op0 = out + ((size_t)(b*QN + i_r0))*DM + h*DH;
    __half* op1 = out + ((size_t)(b*QN + i_r1))*DM + h*DH;
    #pragma unroll
    for (int nt = 0; nt < 8; nt++) {
        int cc = nt*8 + 2*t4;
        *(__half2*)&op0[cc] = __floats2half2_rn(o[nt][0]*inv0, o[nt][1]*inv0);
        *(__half2*)&op1[cc] = __floats2half2_rn(o[nt][2]*inv1, o[nt][3]*inv1);
    }
}

// ------- residual add + LayerNorm: x=full fp32, xh=half copy ---------------
__global__ __launch_bounds__(256)
void ln_kernel(float* __restrict__ x, __half* __restrict__ xh,
               const float* __restrict__ y,
               const float* __restrict__ gamma, const float* __restrict__ beta) {
    const int row = blockIdx.x;
    const int tid = threadIdx.x;
    __shared__ float red[256];

    float s[4];
    float local = 0.0f;
    #pragma unroll
    for (int kk = 0; kk < 4; kk++) {
        int c = tid + kk*256;
        float val = x[(size_t)row*DM + c] + y[(size_t)row*DM + c];
        s[kk] = val;
        local += val;
    }
    red[tid] = local;
    __syncthreads();
    for (int t = 128; t > 0; t >>= 1) {
        if (tid < t) red[tid] += red[tid+t];
        __syncthreads();
    }
    const float mu = red[0] * (1.0f / DM);
    __syncthreads();

    local = 0.0f;
    #pragma unroll
    for (int kk = 0; kk < 4; kk++) {
        float dlt = s[kk] - mu;
        local += dlt * dlt;
    }
    red[tid] = local;
    __syncthreads();
    for (int t = 128; t > 0; t >>= 1) {
        if (tid < t) red[tid] += red[tid+t];
        __syncthreads();
    }
    const float rstd = rsqrtf(red[0] * (1.0f / DM) + 1e-5f);
    __syncthreads();

    #pragma unroll
    for (int kk = 0; kk < 4; kk++) {
        int c = tid + kk*256;
        float val = (s[kk] - mu) * rstd * gamma[c] + beta[c];
        x [(size_t)row*DM + c] = val;
        xh[(size_t)row*DM + c] = __float2half_rn(val);
    }
}

// ---------------- host orchestration ----------------
static inline void run_gemm(const __half* A, const __half* Bt, const float* bias,
                            void* C, int N, int D, int K, bool gelu, bool hout) {
    int ctas = (K/128) * (N/128);
    if (ctas >= 296) {
        dim3 grid(K/128, N/128);
        if (gelu)      mm_h<true , true , 8><<<grid, 256, MM_SMEM8>>>(A, Bt, bias, C, N, D, K);
        else if (hout) mm_h<false, true , 8><<<grid, 256, MM_SMEM8>>>(A, Bt, bias, C, N, D, K);
        else           mm_h<false, false, 8><<<grid, 256, MM_SMEM8>>>(A, Bt, bias, C, N, D, K);
    } else {
        dim3 grid(K/64, N/128);
        if (gelu)      mm_h<true , true , 4><<<grid, 256, MM_SMEM4>>>(A, Bt, bias, C, N, D, K);
        else if (hout) mm_h<false, true , 4><<<grid, 256, MM_SMEM4>>>(A, Bt, bias, C, N, D, K);
        else           mm_h<false, false, 4><<<grid, 256, MM_SMEM4>>>(A, Bt, bias, C, N, D, K);
    }
}

extern "C" void kernel_launch(void* const* d_in, const int* in_sizes, int n_in,
                              void* d_out, int out_size) {
    const float* enc    = (const float*)d_in[0];
    const float* mems   = (const float*)d_in[1];
    const float* emb    = (const float*)d_in[2];
    const float* u      = (const float*)d_in[3];
    const float* vpar   = (const float*)d_in[4];
    const float* saWq   = (const float*)d_in[5];
    const float* saWk   = (const float*)d_in[6];
    const float* saWv   = (const float*)d_in[7];
    const float* saWr   = (const float*)d_in[8];
    const float* safcW  = (const float*)d_in[9];
    const float* safcB  = (const float*)d_in[10];
    const float* ln1g   = (const float*)d_in[11];
    const float* ln1b   = (const float*)d_in[12];
    const float* caWq   = (const float*)d_in[13];
    const float* caWk   = (const float*)d_in[14];
    const float* caWv   = (const float*)d_in[15];
    const float* cafcW  = (const float*)d_in[16];
    const float* cafcB  = (const float*)d_in[17];
    const float* ln2g   = (const float*)d_in[18];
    const float* ln2b   = (const float*)d_in[19];
    const float* ffW1   = (const float*)d_in[20];
    const float* ffb1   = (const float*)d_in[21];
    const float* ffW2   = (const float*)d_in[22];
    const float* ffb2   = (const float*)d_in[23];
    const float* ln3g   = (const float*)d_in[24];
    const float* ln3b   = (const float*)d_in[25];
    const float* outW   = (const float*)d_in[26];
    const int*   ids    = (const int*)  d_in[27];
    float* out = (float*)d_out;

    float *x, *tmp, *bdb;
    __half *hxh, *hmem, *hqkv, *hcakv, *hr4, *hatt, *hq, *hff, *hremb, *henc;
    __half *wqkvh, *wcakvh, *wr4h, *wsafch, *wcafch, *wcaqh, *wff1h, *wff2h, *wouth;
    cudaGetSymbolAddress((void**)&x,      g_x);
    cudaGetSymbolAddress((void**)&tmp,    g_tmp);
    cudaGetSymbolAddress((void**)&bdb,    g_bd);
    cudaGetSymbolAddress((void**)&hxh,    g_hxh);
    cudaGetSymbolAddress((void**)&hmem,   g_hmem);
    cudaGetSymbolAddress((void**)&hqkv,   g_hqkv);
    cudaGetSymbolAddress((void**)&hcakv,  g_hcakv);
    cudaGetSymbolAddress((void**)&hr4,    g_hr4);
    cudaGetSymbolAddress((void**)&hatt,   g_hatt);
    cudaGetSymbolAddress((void**)&hq,     g_hq);
    cudaGetSymbolAddress((void**)&hff,    g_hff);
    cudaGetSymbolAddress((void**)&hremb,  g_hremb);
    cudaGetSymbolAddress((void**)&henc,   g_henc);
    cudaGetSymbolAddress((void**)&wqkvh,  g_wqkv);
    cudaGetSymbolAddress((void**)&wcakvh, g_wcakv);
    cudaGetSymbolAddress((void**)&wr4h,   g_wr4);
    cudaGetSymbolAddress((void**)&wsafch, g_wsafc);
    cudaGetSymbolAddress((void**)&wcafch, g_wcafc);
    cudaGetSymbolAddress((void**)&wcaqh,  g_wcaq);
    cudaGetSymbolAddress((void**)&wff1h,  g_wff1);
    cudaGetSymbolAddress((void**)&wff2h,  g_wff2);
    cudaGetSymbolAddress((void**)&wouth,  g_wout);

    static int smem_set = 0;
    if (!smem_set) {
        cudaFuncSetAttribute(flashmma, cudaFuncAttributeMaxDynamicSharedMemorySize,
                             FLASH_SMEM);
        cudaFuncSetAttribute((mm_h<true , true , 8>), cudaFuncAttributeMaxDynamicSharedMemorySize, MM_SMEM8);
        cudaFuncSetAttribute((mm_h<false, true , 8>), cudaFuncAttributeMaxDynamicSharedMemorySize, MM_SMEM8);
        cudaFuncSetAttribute((mm_h<false, false, 8>), cudaFuncAttributeMaxDynamicSharedMemorySize, MM_SMEM8);
        cudaFuncSetAttribute((mm_h<true , true , 4>), cudaFuncAttributeMaxDynamicSharedMemorySize, MM_SMEM4);
        cudaFuncSetAttribute((mm_h<false, true , 4>), cudaFuncAttributeMaxDynamicSharedMemorySize, MM_SMEM4);
        cudaFuncSetAttribute((mm_h<false, false, 4>), cudaFuncAttributeMaxDynamicSharedMemorySize, MM_SMEM4);
        smem_set = 1;
    }

    // transposed half weights (Bt = W^T, [n][k] row-major)
    dim3 tb(32, 8);
    trans_half<<<dim3(DM/32, DM/32, LNUM), tb>>>(saWq, wqkvh,                   DM, DM, (size_t)DM*DM, (size_t)3072*DM);
    trans_half<<<dim3(DM/32, DM/32, LNUM), tb>>>(saWk, wqkvh + (size_t)1024*DM, DM, DM, (size_t)DM*DM, (size_t)3072*DM);
    trans_half<<<dim3(DM/32, DM/32, LNUM), tb>>>(saWv, wqkvh + (size_t)2048*DM, DM, DM, (size_t)DM*DM, (size_t)3072*DM);
    trans_half<<<dim3(DM/32, DM/32, LNUM), tb>>>(caWk, wcakvh,                  DM, DM, (size_t)DM*DM, (size_t)2048*DM);
    trans_half<<<dim3(DM/32, DM/32, LNUM), tb>>>(caWv, wcakvh + (size_t)1024*DM,DM, DM, (size_t)DM*DM, (size_t)2048*DM);
    trans_half<<<dim3(DM/32, DM/32, LNUM), tb>>>(saWr,  wr4h,   DM, DM, (size_t)DM*DM, (size_t)DM*DM);
    trans_half<<<dim3(DM/32, DM/32, LNUM), tb>>>(safcW, wsafch, DM, DM, (size_t)DM*DM, (size_t)DM*DM);
    trans_half<<<dim3(DM/32, DM/32, LNUM), tb>>>(cafcW, wcafch, DM, DM, (size_t)DM*DM, (size_t)DM*DM);
    trans_half<<<dim3(DM/32, DM/32, LNUM), tb>>>(caWq,  wcaqh,  DM, DM, (size_t)DM*DM, (size_t)DM*DM);
    trans_half<<<dim3(FFN/32, DM/32, LNUM), tb>>>(ffW1, wff1h,  DM, FFN, (size_t)DM*FFN, (size_t)DM*FFN);
    trans_half<<<dim3(DM/32, FFN/32, LNUM), tb>>>(ffW2, wff2h,  FFN, DM, (size_t)DM*FFN, (size_t)DM*FFN);
    trans_half<<<dim3(VN/32, DM/32, 1),     tb>>>(outW, wouth,  DM, VN, 0, 0);
    half_copy<<<((BN*EN*DM/4) + 255)/256, 256>>>(enc, henc, BN*EN*DM/4);

    embed_kernel<<<(BN*QN*DM + 255)/256, 256>>>(ids, emb, x);
    remb_kernel <<<(KLEN*DM + 255)/256, 256>>>(hremb);

    // layer-independent projections (fused across layers)
    run_gemm(hremb, wr4h,   nullptr, hr4,   KLEN,  DM, 4096, false, true);
    run_gemm(henc,  wcakvh, nullptr, hcakv, BN*EN, DM, 8192, false, true);

    dim3 flash_grid(QN/128, HN, BN);
    dim3 bd_grid(KLEN/64, QN/128, BN*HN);

    for (int l = 0; l < LNUM; l++) {
        // ---- self-attention (TransformerXL relative) ----
        concat_kernel<<<(BN*KLEN*DM + 255)/256, 256>>>(
            mems + (size_t)l*BN*MN*DM, x, hmem);

        run_gemm(hmem, wqkvh + (size_t)l*3072*DM, nullptr, hqkv,
                 BN*KLEN, DM, 3072, false, true);

        const __half* qself = hqkv + (size_t)MN*3072;
        bd_mma<<<bd_grid, 256>>>(qself, 3072, (size_t)KLEN*3072,
                                 hr4 + (size_t)l*1024, 4096, vpar, bdb);
        flashmma<<<flash_grid, 256, FLASH_SMEM>>>(
            qself, 3072, (size_t)KLEN*3072,
            hqkv + 1024, hqkv + 2048, 3072, (size_t)KLEN*3072,
            bdb, u, hatt, KLEN, 1);

        run_gemm(hatt, wsafch + (size_t)l*DM*DM, safcB + (size_t)l*DM,
                 tmp, BN*QN, DM, DM, false, false);
        ln_kernel<<<BN*QN, 256>>>(x, hxh, tmp, ln1g + (size_t)l*DM, ln1b + (size_t)l*DM);

        // ---- cross-attention ----
        run_gemm(hxh, wcaqh + (size_t)l*DM*DM, nullptr, hq, BN*QN, DM, DM, false, true);

        flashmma<<<flash_grid, 256, FLASH_SMEM>>>(
            hq, DM, (size_t)QN*DM,
            hcakv + (size_t)l*2048, hcakv + (size_t)l*2048 + 1024,
            8192, (size_t)EN*8192,
            nullptr, nullptr, hatt, EN, 0);

        run_gemm(hatt, wcafch + (size_t)l*DM*DM, cafcB + (size_t)l*DM,
                 tmp, BN*QN, DM, DM, false, false);
        ln_kernel<<<BN*QN, 256>>>(x, hxh, tmp, ln2g + (size_t)l*DM, ln2b + (size_t)l*DM);

        // ---- feed-forward ----
        run_gemm(hxh, wff1h + (size_t)l*DM*FFN, ffb1 + (size_t)l*FFN,
                 hff, BN*QN, DM, FFN, true, true);
        run_gemm(hff, wff2h + (size_t)l*DM*FFN, ffb2 + (size_t)l*DM,
                 tmp, BN*QN, FFN, DM, false, false);
        ln_kernel<<<BN*QN, 256>>>(x, hxh, tmp, ln3g + (size_t)l*DM, ln3b + (size_t)l*DM);
    }

    // ---- output projection ----
    run_gemm(hxh, wouth, nullptr, out, BN*QN, DM, VN, false, false);
}

// round 12
// speedup vs baseline: 1.0706x; 1.0706x over previous
#include <cuda_runtime.h>
#include <cuda_fp16.h>
#include <math.h>
#include <stdint.h>

// Problem constants
#define LNUM 4
#define DM   1024
#define HN   16
#define DH   64
#define FFN  4096
#define VN   8192
#define BN   4
#define QN   512
#define MN   512
#define EN   512
#define KLEN 1024   // M + Q

// ---------------- scratch (device globals; no allocation) ----------------
__device__ float  g_x   [BN*QN*DM];         // residual stream (full fp32)
__device__ float  g_tmp [BN*QN*DM];
__device__ float  g_bd  [BN*HN*QN*KLEN];
// half activation buffers
__device__ __half g_hxh  [BN*QN*DM];
__device__ __half g_hmem [BN*KLEN*DM];
__device__ __half g_hqkv [BN*KLEN*3072];
__device__ __half g_hcakv[BN*EN*8192];
__device__ __half g_hr4  [KLEN*4096];
__device__ __half g_hatt [BN*QN*DM];
__device__ __half g_hq   [BN*QN*DM];
__device__ __half g_hff  [BN*QN*FFN];
__device__ __half g_hremb[KLEN*DM];
__device__ __half g_henc [BN*EN*DM];
// transposed half weights (B^T, [n][k] row-major), built per call
__device__ __half g_wqkv [LNUM*3072*DM];
__device__ __half g_wcakv[8192*DM];
__device__ __half g_wr4  [4096*DM];
__device__ __half g_wsafc[LNUM*DM*DM];
__device__ __half g_wcafc[LNUM*DM*DM];
__device__ __half g_wcaq [LNUM*DM*DM];
__device__ __half g_wff1 [LNUM*FFN*DM];
__device__ __half g_wff2 [LNUM*DM*FFN];
__device__ __half g_wout [VN*DM];

// ---------------- helpers ----------------
__device__ __forceinline__ unsigned f2tf(float x) {
    unsigned u; asm("cvt.rna.tf32.f32 %0, %1;" : "=r"(u) : "f"(x)); return u;
}

#define MMA_TF32(C, A, B0, B1)                                                \
    asm volatile(                                                             \
        "mma.sync.aligned.m16n8k8.row.col.f32.tf32.tf32.f32 "                 \
        "{%0,%1,%2,%3}, {%4,%5,%6,%7}, {%8,%9}, {%0,%1,%2,%3};"               \
        : "+f"((C)[0]), "+f"((C)[1]), "+f"((C)[2]), "+f"((C)[3])              \
        : "r"((A)[0]), "r"((A)[1]), "r"((A)[2]), "r"((A)[3]),                 \
          "r"(B0), "r"(B1))

#define MMA_F16(C, A0, A1, A2, A3, B0, B1)                                    \
    asm volatile(                                                             \
        "mma.sync.aligned.m16n8k16.row.col.f32.f16.f16.f32 "                  \
        "{%0,%1,%2,%3}, {%4,%5,%6,%7}, {%8,%9}, {%0,%1,%2,%3};"               \
        : "+f"((C)[0]), "+f"((C)[1]), "+f"((C)[2]), "+f"((C)[3])              \
        : "r"(A0), "r"(A1), "r"(A2), "r"(A3), "r"(B0), "r"(B1))

__device__ __forceinline__ void cp16(uint32_t dst, const void* src) {
    asm volatile("cp.async.cg.shared.global [%0], [%1], 16;\n" :: "r"(dst), "l"(src));
}
#define CP_COMMIT()  asm volatile("cp.async.commit_group;\n" ::)

__device__ __forceinline__ uint32_t smem_u32(const void* p) {
    uint32_t a;
    asm("{ .reg .u64 t; cvta.to.shared.u64 t, %1; cvt.u32.u64 %0, t; }"
        : "=r"(a) : "l"(p));
    return a;
}
__device__ __forceinline__ uint32_t packh2(float a, float b) {
    __half2 h = __floats2half2_rn(a, b);
    return *(uint32_t*)&h;
}

// ---------------- elementwise kernels ----------------
__global__ void half_copy(const float* __restrict__ src,
                          __half* __restrict__ dst, int n4) {
    int i = blockIdx.x * blockDim.x + threadIdx.x;
    if (i >= n4) return;
    float4 v = ((const float4*)src)[i];
    ((__half2*)dst)[2*i]   = __floats2half2_rn(v.x, v.y);
    ((__half2*)dst)[2*i+1] = __floats2half2_rn(v.z, v.w);
}

// transpose + half: src [R, C] fp32 row-major -> dst [C, R] half row-major
__global__ void trans_half(const float* __restrict__ src, __half* __restrict__ dst,
                           int R, int C, size_t sbs, size_t dbs) {
    __shared__ float t[32][33];
    const float* s = src + (size_t)blockIdx.z * sbs;
    __half*      d = dst + (size_t)blockIdx.z * dbs;
    int c0 = blockIdx.x * 32, r0 = blockIdx.y * 32;
    int tx = threadIdx.x, ty = threadIdx.y;
    #pragma unroll
    for (int i = 0; i < 4; i++)
        t[ty + 8*i][tx] = s[(size_t)(r0 + ty + 8*i) * C + c0 + tx];
    __syncthreads();
    #pragma unroll
    for (int i = 0; i < 4; i++)
        d[(size_t)(c0 + ty + 8*i) * R + r0 + tx] = __float2half_rn(t[tx][ty + 8*i]);
}

__global__ void embed_kernel(const int* __restrict__ ids,
                             const float* __restrict__ emb,
                             float* __restrict__ x) {
    int idx = blockIdx.x * blockDim.x + threadIdx.x;
    if (idx >= BN*QN*DM) return;
    int row = idx / DM;
    int d   = idx - row * DM;
    int tok = ids[row];
    x[idx] = emb[tok * DM + d] * 32.0f;
}

__global__ void remb_kernel(__half* __restrict__ remb) {
    int idx = blockIdx.x * blockDim.x + threadIdx.x;
    if (idx >= KLEN*DM) return;
    int p = idx / DM;
    int d = idx - p * DM;
    float pos = (float)(KLEN - 1 - p);
    int k = (d < DM/2) ? d : d - DM/2;
    float invf = powf(10000.0f, -(float)k / (float)(DM/2));
    float a = pos * invf;
    remb[idx] = __float2half_rn((d < DM/2) ? sinf(a) : cosf(a));
}

__global__ void concat_kernel(const float* __restrict__ mems_l,
                              const float* __restrict__ x,
                              __half* __restrict__ mem) {
    int idx = blockIdx.x * blockDim.x + threadIdx.x;
    if (idx >= BN*KLEN*DM) return;
    int d   = idx % DM;
    int rem = idx / DM;
    int j   = rem % KLEN;
    int b   = rem / KLEN;
    float val;
    if (j < MN) val = mems_l[(b*MN + j)*DM + d];
    else        val = x[(b*QN + (j - MN))*DM + d];
    mem[idx] = __float2half_rn(val);
}

// ---------------- fp16 tensor-core GEMM, 4-stage cp.async, 2 CTAs/SM -------
// C[N,K] = A[N,D] @ W[D,K]; Bt = W^T as half [K, D] row-major. (R10 kernel)
#define STG    4
#define ROWU   12
#define TILE_U (128*ROWU)
#define STAGE_U (2*TILE_U)
#define MM_SMEM (STG*STAGE_U*4)

template<bool GELU, bool HOUT>
__global__ __launch_bounds__(256, 2)
void mm_h(const __half* __restrict__ A, const __half* __restrict__ Bt,
          const float* __restrict__ bias, void* __restrict__ Cout,
          int N, int D, int K) {
    extern __shared__ uint32_t smu[];
    const uint32_t sb = smem_u32(smu);

    const int tid  = threadIdx.x;
    const int row0 = blockIdx.y * 128, col0 = blockIdx.x * 128;
    const int lane = tid & 31, wid = tid >> 5;
    const int grp  = lane >> 2, t4 = lane & 3;
    const int wm   = (wid & 3) * 32, wn = (wid >> 2) * 64;

    const int lrow = tid >> 1;
    const int lseg = tid & 1;
    const __half* Ag = A  + (size_t)(row0 + lrow) * D + lseg * 8;
    const __half* Bg = Bt + (size_t)(col0 + lrow) * D + lseg * 8;
    const uint32_t dstA = sb + (lrow*ROWU + lseg*4) * 4;
    const uint32_t dstB = dstA + TILE_U*4;

    const int KT = D >> 4;

    float c[2][8][4];
    #pragma unroll
    for (int i = 0; i < 2; i++)
        #pragma unroll
        for (int j = 0; j < 8; j++)
            #pragma unroll
            for (int t = 0; t < 4; t++) c[i][j][t] = 0.0f;

    #pragma unroll
    for (int s = 0; s < STG-1; s++) {
        cp16(dstA + s*STAGE_U*4, Ag + (size_t)s*16);
        cp16(dstB + s*STAGE_U*4, Bg + (size_t)s*16);
        CP_COMMIT();
    }

    for (int kt = 0; kt < KT; kt++) {
        asm volatile("cp.async.wait_group 2;\n" ::);
        __syncthreads();
        const int st = kt & (STG-1);
        const uint32_t* AsU = smu + st*STAGE_U;
        const uint32_t* BsU = AsU + TILE_U;

        uint32_t af[2][4], bf[8][2];
        #pragma unroll
        for (int mt = 0; mt < 2; mt++) {
            const int m = wm + mt*16 + grp;
            af[mt][0] = AsU[(m  )*ROWU + t4    ];
            af[mt][1] = AsU[(m+8)*ROWU + t4    ];
            af[mt][2] = AsU[(m  )*ROWU + t4 + 4];
            af[mt][3] = AsU[(m+8)*ROWU + t4 + 4];
        }
        #pragma unroll
        for (int nt = 0; nt < 8; nt++) {
            const int n = wn + nt*8 + grp;
            bf[nt][0] = BsU[n*ROWU + t4    ];
            bf[nt][1] = BsU[n*ROWU + t4 + 4];
        }

        const int kn = kt + STG - 1;
        if (kn < KT) {
            const int sn = kn & (STG-1);
            cp16(dstA + sn*STAGE_U*4, Ag + (size_t)kn*16);
            cp16(dstB + sn*STAGE_U*4, Bg + (size_t)kn*16);
        }
        CP_COMMIT();

        #pragma unroll
        for (int mt = 0; mt < 2; mt++)
            #pragma unroll
            for (int nt = 0; nt < 8; nt++)
                MMA_F16(c[mt][nt], af[mt][0], af[mt][1], af[mt][2], af[mt][3],
                        bf[nt][0], bf[nt][1]);
    }

    #pragma unroll
    for (int mt = 0; mt < 2; mt++)
        #pragma unroll
        for (int nt = 0; nt < 8; nt++) {
            int r  = row0 + wm + mt*16 + grp;
            int cc = col0 + wn + nt*8 + t4*2;
            #pragma unroll
            for (int half = 0; half < 2; half++) {
                int rr = r + half*8;
                float v0 = c[mt][nt][half*2 + 0];
                float v1 = c[mt][nt][half*2 + 1];
                if (bias) { v0 += bias[cc]; v1 += bias[cc+1]; }
                if (GELU) {
                    v0 = 0.5f*v0*(1.0f + erff(v0*0.70710678118654752f));
                    v1 = 0.5f*v1*(1.0f + erff(v1*0.70710678118654752f));
                }
                if (HOUT) {
                    __half* Ch = (__half*)Cout;
                    *(__half2*)&Ch[(size_t)rr*K + cc] = __floats2half2_rn(v0, v1);
                } else {
                    float* Cf = (float*)Cout;
                    *(float2*)&Cf[(size_t)rr*K + cc] = make_float2(v0, v1);
                }
            }
        }
}

// ---------------- BD_raw via fp16 tensor cores ----------------
#define RS_WSTR 36
__global__ __launch_bounds__(256)
void bd_mma(const __half* __restrict__ q, int qrs, size_t qbs,
            const __half* __restrict__ r, int rrs,
            const float* __restrict__ vvec, float* __restrict__ bdout) {
    __shared__ uint32_t RsU[64*RS_WSTR];
    const int t0 = blockIdx.x * 64;
    const int i0 = blockIdx.y * 128;
    const int h = blockIdx.z & (HN-1), b = blockIdx.z >> 4;
    const int tid = threadIdx.x;
    const int lane = tid & 31, wid = tid >> 5;
    const int grp = lane >> 2, t4 = lane & 3;
    const int i_r0 = i0 + wid*16 + grp, i_r1 = i_r0 + 8;

    uint32_t qf[4][4];
    {
        const __half* qp0 = q + (size_t)b*qbs + (size_t)i_r0*qrs + h*DH;
        const __half* qp1 = q + (size_t)b*qbs + (size_t)i_r1*qrs + h*DH;
        const float* up  = vvec + h*DH;
        #pragma unroll
        for (int ks = 0; ks < 4; ks++) {
            int k0 = 16*ks + 2*t4;
            float ua = up[k0], ub = up[k0+1], uc = up[k0+8], ud = up[k0+9];
            qf[ks][0] = packh2(__half2float(qp0[k0])   + ua, __half2float(qp0[k0+1]) + ub);
            qf[ks][1] = packh2(__half2float(qp1[k0])   + ua, __half2float(qp1[k0+1]) + ub);
            qf[ks][2] = packh2(__half2float(qp0[k0+8]) + uc, __half2float(qp0[k0+9]) + ud);
            qf[ks][3] = packh2(__half2float(qp1[k0+8]) + uc, __half2float(qp1[k0+9]) + ud);
        }
    }
    #pragma unroll
    for (int t = 0; t < 2; t++) {
        int idx = tid + 256*t;
        int row = idx >> 3, c8 = (idx & 7) * 8;
        uint4 rv = *(const uint4*)&r[(size_t)(t0 + row)*rrs + h*DH + c8];
        *(uint4*)&RsU[row*RS_WSTR + (idx & 7)*4] = rv;
    }
    __syncthreads();

    float s[8][4];
    #pragma unroll
    for (int nt = 0; nt < 8; nt++)
        #pragma unroll
        for (int e = 0; e < 4; e++) s[nt][e] = 0.0f;

    #pragma unroll
    for (int ks = 0; ks < 4; ks++)
        #pragma unroll
        for (int nt = 0; nt < 8; nt++) {
            uint32_t b0 = RsU[(nt*8+grp)*RS_WSTR + t4 + 8*ks];
            uint32_t b1 = RsU[(nt*8+grp)*RS_WSTR + t4 + 4 + 8*ks];
            MMA_F16(s[nt], qf[ks][0], qf[ks][1], qf[ks][2], qf[ks][3], b0, b1);
        }

    float* o0 = bdout + (((size_t)(b*HN + h))*QN + i_r0)*KLEN + t0;
    float* o1 = bdout + (((size_t)(b*HN + h))*QN + i_r1)*KLEN + t0;
    #pragma unroll
    for (int nt = 0; nt < 8; nt++) {
        int cc = nt*8 + 2*t4;
        *(float2*)&o0[cc] = make_float2(s[nt][0], s[nt][1]);
        *(float2*)&o1[cc] = make_float2(s[nt][2], s[nt][3]);
    }
}

// ---------------- MMA flash attention: fp16 QK^T, tf32 PV ----------------
#define KS_WSTR 36
#define VS_STRIDE 72
#define PS_STRIDE 68
#define FLASH_SMEM ((64*KS_WSTR + 64*VS_STRIDE + 128*PS_STRIDE) * 4)

__global__ __launch_bounds__(256)
void flashmma(const __half* __restrict__ q, int qrs, size_t qbs,
              const __half* __restrict__ k, const __half* __restrict__ v,
              int kvrs, size_t kvbs,
              const float* __restrict__ bd, const float* __restrict__ uvec,
              __half* __restrict__ out, int klen, int useMask) {
    extern __shared__ uint32_t smu[];
    uint32_t* KsU = smu;
    float* Vs = (float*)(smu + 64*KS_WSTR);
    float* Ps = Vs + 64*VS_STRIDE;

    const int i0 = blockIdx.x * 128;
    const int h = blockIdx.y, b = blockIdx.z;
    const int tid = threadIdx.x;
    const int lane = tid & 31, wid = tid >> 5;
    const int grp = lane >> 2, t4 = lane & 3;
    const int r0 = wid*16 + grp, r1 = r0 + 8;
    const int i_r0 = i0 + r0, i_r1 = i0 + r1;

    uint32_t qf[4][4];
    {
        const __half* qp0 = q + (size_t)b*qbs + (size_t)i_r0*qrs + h*DH;
        const __half* qp1 = q + (size_t)b*qbs + (size_t)i_r1*qrs + h*DH;
        #pragma unroll
        for (int ks = 0; ks < 4; ks++) {
            int k0 = 16*ks + 2*t4;
            float ua = uvec ? uvec[h*DH + k0]   : 0.0f;
            float ub = uvec ? uvec[h*DH + k0+1] : 0.0f;
            float uc = uvec ? uvec[h*DH + k0+8] : 0.0f;
            float ud = uvec ? uvec[h*DH + k0+9] : 0.0f;
            qf[ks][0] = packh2(__half2float(qp0[k0])   + ua, __half2float(qp0[k0+1]) + ub);
            qf[ks][1] = packh2(__half2float(qp1[k0])   + ua, __half2float(qp1[k0+1]) + ub);
            qf[ks][2] = packh2(__half2float(qp0[k0+8]) + uc, __half2float(qp0[k0+9]) + ud);
            qf[ks][3] = packh2(__half2float(qp1[k0+8]) + uc, __half2float(qp1[k0+9]) + ud);
        }
    }

    float m0 = -INFINITY, m1 = -INFINITY, l0 = 0.0f, l1 = 0.0f;
    float o[8][4];
    #pragma unroll
    for (int nt = 0; nt < 8; nt++)
        #pragma unroll
        for (int e = 0; e < 4; e++) o[nt][e] = 0.0f;

    const float* bdr0 = bd ? bd + (((size_t)(b*HN + h))*QN + i_r0)*KLEN : (const float*)0;
    const float* bdr1 = bd ? bd + (((size_t)(b*HN + h))*QN + i_r1)*KLEN : (const float*)0;

    int lastj = klen - 1;
    if (useMask) { int lm = i0 + 127 + MN; if (lm < lastj) lastj = lm; }

    for (int j0 = 0; j0 <= lastj; j0 += 64) {
        __syncthreads();
        #pragma unroll
        for (int t = 0; t < 2; t++) {
            int idx = tid + 256*t;
            int row = idx >> 3, c8 = (idx & 7) * 8;
            size_t gb = (size_t)b*kvbs + (size_t)(j0 + row)*kvrs + h*DH + c8;
            uint4 kv = *(const uint4*)&k[gb];
            uint4 vv = *(const uint4*)&v[gb];
            *(uint4*)&KsU[row*KS_WSTR + (idx & 7)*4] = kv;
            float* vd = Vs + row*VS_STRIDE + c8;
            float2 f0 = __half22float2(*(__half2*)&vv.x);
            float2 f1 = __half22float2(*((__half2*)&vv.x + 1));
            float2 f2 = __half22float2(*(__half2*)&vv.z);
            float2 f3 = __half22float2(*((__half2*)&vv.z + 1));
            vd[0]=f0.x; vd[1]=f0.y; vd[2]=f1.x; vd[3]=f1.y;
            vd[4]=f2.x; vd[5]=f2.y; vd[6]=f3.x; vd[7]=f3.y;
        }
        __syncthreads();

        float bdv[8][4];
        if (bd) {
            #pragma unroll
            for (int nt = 0; nt < 8; nt++) {
                int jA = j0 + nt*8 + 2*t4;
                int jr0 = jA - i_r0 + (QN-1);
                int jr1 = jA - i_r1 + (QN-1);
                jr0 = max(0, min(KLEN-2, jr0));
                jr1 = max(0, min(KLEN-2, jr1));
                bdv[nt][0] = bdr0[jr0];   bdv[nt][1] = bdr0[jr0+1];
                bdv[nt][2] = bdr1[jr1];   bdv[nt][3] = bdr1[jr1+1];
            }
        }

        float s[8][4];
        #pragma unroll
        for (int nt = 0; nt < 8; nt++)
            #pragma unroll
            for (int e = 0; e < 4; e++) s[nt][e] = 0.0f;
        #pragma unroll
        for (int ks = 0; ks < 4; ks++)
            #pragma unroll
            for (int nt = 0; nt < 8; nt++) {
                uint32_t b0 = KsU[(nt*8+grp)*KS_WSTR + t4 + 8*ks];
                uint32_t b1 = KsU[(nt*8+grp)*KS_WSTR + t4 + 4 + 8*ks];
                MMA_F16(s[nt], qf[ks][0], qf[ks][1], qf[ks][2], qf[ks][3], b0, b1);
            }

        float mc0 = -INFINITY, mc1 = -INFINITY;
        #pragma unroll
        for (int nt = 0; nt < 8; nt++) {
            int jA = j0 + nt*8 + 2*t4;
            int jB = jA + 1;
            float v0 = s[nt][0], v1 = s[nt][1], v2 = s[nt][2], v3 = s[nt][3];
            if (bd) { v0 += bdv[nt][0]; v1 += bdv[nt][1]; v2 += bdv[nt][2]; v3 += bdv[nt][3]; }
            v0 *= 0.125f; v1 *= 0.125f; v2 *= 0.125f; v3 *= 0.125f;
            if (useMask) {
                if (jA > i_r0 + MN) v0 = -INFINITY;
                if (jB > i_r0 + MN) v1 = -INFINITY;
                if (jA > i_r1 + MN) v2 = -INFINITY;
                if (jB > i_r1 + MN) v3 = -INFINITY;
            }
            s[nt][0]=v0; s[nt][1]=v1; s[nt][2]=v2; s[nt][3]=v3;
            mc0 = fmaxf(mc0, fmaxf(v0, v1));
            mc1 = fmaxf(mc1, fmaxf(v2, v3));
        }
        mc0 = fmaxf(mc0, __shfl_xor_sync(0xffffffffu, mc0, 1));
        mc0 = fmaxf(mc0, __shfl_xor_sync(0xffffffffu, mc0, 2));
        mc1 = fmaxf(mc1, __shfl_xor_sync(0xffffffffu, mc1, 1));
        mc1 = fmaxf(mc1, __shfl_xor_sync(0xffffffffu, mc1, 2));

        float nm0 = fmaxf(m0, mc0), nm1 = fmaxf(m1, mc1);
        float corr0 = __expf(m0 - nm0), corr1 = __expf(m1 - nm1);
        float ps0 = 0.0f, ps1 = 0.0f;
        #pragma unroll
        for (int nt = 0; nt < 8; nt++) {
            float p0 = __expf(s[nt][0] - nm0);
            float p1 = __expf(s[nt][1] - nm0);
            float p2 = __expf(s[nt][2] - nm1);
            float p3 = __expf(s[nt][3] - nm1);
            ps0 += p0 + p1; ps1 += p2 + p3;
            int cc = nt*8 + 2*t4;
            Ps[r0*PS_STRIDE + cc]     = __uint_as_float(f2tf(p0));
            Ps[r0*PS_STRIDE + cc + 1] = __uint_as_float(f2tf(p1));
            Ps[r1*PS_STRIDE + cc]     = __uint_as_float(f2tf(p2));
            Ps[r1*PS_STRIDE + cc + 1] = __uint_as_float(f2tf(p3));
        }
        ps0 += __shfl_xor_sync(0xffffffffu, ps0, 1);
        ps0 += __shfl_xor_sync(0xffffffffu, ps0, 2);
        ps1 += __shfl_xor_sync(0xffffffffu, ps1, 1);
        ps1 += __shfl_xor_sync(0xffffffffu, ps1, 2);
        l0 = l0 * corr0 + ps0;  m0 = nm0;
        l1 = l1 * corr1 + ps1;  m1 = nm1;
        #pragma unroll
        for (int nt = 0; nt < 8; nt++) {
            o[nt][0] *= corr0; o[nt][1] *= corr0;
            o[nt][2] *= corr1; o[nt][3] *= corr1;
        }
        __syncwarp();

        #pragma unroll
        for (int ks = 0; ks < 8; ks++) {
            unsigned a[4];
            a[0] = __float_as_uint(Ps[r0*PS_STRIDE + ks*8 + t4]);
            a[1] = __float_as_uint(Ps[r1*PS_STRIDE + ks*8 + t4]);
            a[2] = __float_as_uint(Ps[r0*PS_STRIDE + ks*8 + t4 + 4]);
            a[3] = __float_as_uint(Ps[r1*PS_STRIDE + ks*8 + t4 + 4]);
            #pragma unroll
            for (int nt = 0; nt < 8; nt++) {
                unsigned b0 = __float_as_uint(Vs[(ks*8+t4)*VS_STRIDE + nt*8 + grp]);
                unsigned b1 = __float_as_uint(Vs[(ks*8+t4+4)*VS_STRIDE + nt*8 + grp]);
                MMA_TF32(o[nt], a, b0, b1);
            }
        }
    }

    const float inv0 = 1.0f / l0, inv1 = 1.0f / l1;
    __half* op0 = out + ((size_t)(b*QN + i_r0))*DM + h*DH;
    __half* op1 = out + ((size_t)(b*QN + i_r1))*DM + h*DH;
    #pragma unroll
    for (int nt = 0; nt < 8; nt++) {
        int cc = nt*8 + 2*t4;
        *(__half2*)&op0[cc] = __floats2half2_rn(o[nt][0]*inv0, o[nt][1]*inv0);
        *(__half2*)&op1[cc] = __floats2half2_rn(o[nt][2]*inv1, o[nt][3]*inv1);
    }
}

// ------- residual add + LayerNorm (single-pass shuffle reduction) ----------
__global__ __launch_bounds__(256)
void ln_kernel(float* __restrict__ x, __half* __restrict__ xh,
               const float* __restrict__ y,
               const float* __restrict__ gamma, const float* __restrict__ beta) {
    const int row = blockIdx.x;
    const int tid = threadIdx.x;
    const int lane = tid & 31, wid = tid >> 5;
    __shared__ float rs[8], rq[8];

    float s[4];
    float sum = 0.0f, sq = 0.0f;
    #pragma unroll
    for (int kk = 0; kk < 4; kk++) {
        int c = tid + kk*256;
        float val = x[(size_t)row*DM + c] + y[(size_t)row*DM + c];
        s[kk] = val;
        sum += val;
        sq  = fmaf(val, val, sq);
    }
    #pragma unroll
    for (int d = 16; d > 0; d >>= 1) {
        sum += __shfl_xor_sync(0xffffffffu, sum, d);
        sq  += __shfl_xor_sync(0xffffffffu, sq,  d);
    }
    if (lane == 0) { rs[wid] = sum; rq[wid] = sq; }
    __syncthreads();
    float tot = 0.0f, totq = 0.0f;
    #pragma unroll
    for (int w = 0; w < 8; w++) { tot += rs[w]; totq += rq[w]; }
    const float mu = tot * (1.0f / DM);
    const float var = totq * (1.0f / DM) - mu * mu;
    const float rstd = rsqrtf(var + 1e-5f);

    #pragma unroll
    for (int kk = 0; kk < 4; kk++) {
        int c = tid + kk*256;
        float val = (s[kk] - mu) * rstd * gamma[c] + beta[c];
        x [(size_t)row*DM + c] = val;
        xh[(size_t)row*DM + c] = __float2half_rn(val);
    }
}

// ---------------- host orchestration ----------------
static inline void run_gemm(const __half* A, const __half* Bt, const float* bias,
                            void* C, int N, int D, int K, bool gelu, bool hout) {
    dim3 grid(K/128, N/128);
    if (gelu)      mm_h<true , true ><<<grid, 256, MM_SMEM>>>(A, Bt, bias, C, N, D, K);
    else if (hout) mm_h<false, true ><<<grid, 256, MM_SMEM>>>(A, Bt, bias, C, N, D, K);
    else           mm_h<false, false><<<grid, 256, MM_SMEM>>>(A, Bt, bias, C, N, D, K);
}

extern "C" void kernel_launch(void* const* d_in, const int* in_sizes, int n_in,
                              void* d_out, int out_size) {
    const float* enc    = (const float*)d_in[0];
    const float* mems   = (const float*)d_in[1];
    const float* emb    = (const float*)d_in[2];
    const float* u      = (const float*)d_in[3];
    const float* vpar   = (const float*)d_in[4];
    const float* saWq   = (const float*)d_in[5];
    const float* saWk   = (const float*)d_in[6];
    const float* saWv   = (const float*)d_in[7];
    const float* saWr   = (const float*)d_in[8];
    const float* safcW  = (const float*)d_in[9];
    const float* safcB  = (const float*)d_in[10];
    const float* ln1g   = (const float*)d_in[11];
    const float* ln1b   = (const float*)d_in[12];
    const float* caWq   = (const float*)d_in[13];
    const float* caWk   = (const float*)d_in[14];
    const float* caWv   = (const float*)d_in[15];
    const float* cafcW  = (const float*)d_in[16];
    const float* cafcB  = (const float*)d_in[17];
    const float* ln2g   = (const float*)d_in[18];
    const float* ln2b   = (const float*)d_in[19];
    const float* ffW1   = (const float*)d_in[20];
    const float* ffb1   = (const float*)d_in[21];
    const float* ffW2   = (const float*)d_in[22];
    const float* ffb2   = (const float*)d_in[23];
    const float* ln3g   = (const float*)d_in[24];
    const float* ln3b   = (const float*)d_in[25];
    const float* outW   = (const float*)d_in[26];
    const int*   ids    = (const int*)  d_in[27];
    float* out = (float*)d_out;

    float *x, *tmp, *bdb;
    __half *hxh, *hmem, *hqkv, *hcakv, *hr4, *hatt, *hq, *hff, *hremb, *henc;
    __half *wqkvh, *wcakvh, *wr4h, *wsafch, *wcafch, *wcaqh, *wff1h, *wff2h, *wouth;
    cudaGetSymbolAddress((void**)&x,      g_x);
    cudaGetSymbolAddress((void**)&tmp,    g_tmp);
    cudaGetSymbolAddress((void**)&bdb,    g_bd);
    cudaGetSymbolAddress((void**)&hxh,    g_hxh);
    cudaGetSymbolAddress((void**)&hmem,   g_hmem);
    cudaGetSymbolAddress((void**)&hqkv,   g_hqkv);
    cudaGetSymbolAddress((void**)&hcakv,  g_hcakv);
    cudaGetSymbolAddress((void**)&hr4,    g_hr4);
    cudaGetSymbolAddress((void**)&hatt,   g_hatt);
    cudaGetSymbolAddress((void**)&hq,     g_hq);
    cudaGetSymbolAddress((void**)&hff,    g_hff);
    cudaGetSymbolAddress((void**)&hremb,  g_hremb);
    cudaGetSymbolAddress((void**)&henc,   g_henc);
    cudaGetSymbolAddress((void**)&wqkvh,  g_wqkv);
    cudaGetSymbolAddress((void**)&wcakvh, g_wcakv);
    cudaGetSymbolAddress((void**)&wr4h,   g_wr4);
    cudaGetSymbolAddress((void**)&wsafch, g_wsafc);
    cudaGetSymbolAddress((void**)&wcafch, g_wcafc);
    cudaGetSymbolAddress((void**)&wcaqh,  g_wcaq);
    cudaGetSymbolAddress((void**)&wff1h,  g_wff1);
    cudaGetSymbolAddress((void**)&wff2h,  g_wff2);
    cudaGetSymbolAddress((void**)&wouth,  g_wout);

    static int smem_set = 0;
    if (!smem_set) {
        cudaFuncSetAttribute(flashmma, cudaFuncAttributeMaxDynamicSharedMemorySize,
                             FLASH_SMEM);
        cudaFuncSetAttribute((mm_h<true , true >), cudaFuncAttributeMaxDynamicSharedMemorySize, MM_SMEM);
        cudaFuncSetAttribute((mm_h<false, true >), cudaFuncAttributeMaxDynamicSharedMemorySize, MM_SMEM);
        cudaFuncSetAttribute((mm_h<false, false>), cudaFuncAttributeMaxDynamicSharedMemorySize, MM_SMEM);
        smem_set = 1;
    }

    // transposed half weights (Bt = W^T, [n][k] row-major)
    dim3 tb(32, 8);
    trans_half<<<dim3(DM/32, DM/32, LNUM), tb>>>(saWq, wqkvh,                   DM, DM, (size_t)DM*DM, (size_t)3072*DM);
    trans_half<<<dim3(DM/32, DM/32, LNUM), tb>>>(saWk, wqkvh + (size_t)1024*DM, DM, DM, (size_t)DM*DM, (size_t)3072*DM);
    trans_half<<<dim3(DM/32, DM/32, LNUM), tb>>>(saWv, wqkvh + (size_t)2048*DM, DM, DM, (size_t)DM*DM, (size_t)3072*DM);
    trans_half<<<dim3(DM/32, DM/32, LNUM), tb>>>(caWk, wcakvh,                  DM, DM, (size_t)DM*DM, (size_t)2048*DM);
    trans_half<<<dim3(DM/32, DM/32, LNUM), tb>>>(caWv, wcakvh + (size_t)1024*DM,DM, DM, (size_t)DM*DM, (size_t)2048*DM);
    trans_half<<<dim3(DM/32, DM/32, LNUM), tb>>>(saWr,  wr4h,   DM, DM, (size_t)DM*DM, (size_t)DM*DM);
    trans_half<<<dim3(DM/32, DM/32, LNUM), tb>>>(safcW, wsafch, DM, DM, (size_t)DM*DM, (size_t)DM*DM);
    trans_half<<<dim3(DM/32, DM/32, LNUM), tb>>>(cafcW, wcafch, DM, DM, (size_t)DM*DM, (size_t)DM*DM);
    trans_half<<<dim3(DM/32, DM/32, LNUM), tb>>>(caWq,  wcaqh,  DM, DM, (size_t)DM*DM, (size_t)DM*DM);
    trans_half<<<dim3(FFN/32, DM/32, LNUM), tb>>>(ffW1, wff1h,  DM, FFN, (size_t)DM*FFN, (size_t)DM*FFN);
    trans_half<<<dim3(DM/32, FFN/32, LNUM), tb>>>(ffW2, wff2h,  FFN, DM, (size_t)DM*FFN, (size_t)DM*FFN);
    trans_half<<<dim3(VN/32, DM/32, 1),     tb>>>(outW, wouth,  DM, VN, 0, 0);
    half_copy<<<((BN*EN*DM/4) + 255)/256, 256>>>(enc, henc, BN*EN*DM/4);

    embed_kernel<<<(BN*QN*DM + 255)/256, 256>>>(ids, emb, x);
    remb_kernel <<<(KLEN*DM + 255)/256, 256>>>(hremb);

    // layer-independent projections (fused across layers)
    run_gemm(hremb, wr4h,   nullptr, hr4,   KLEN,  DM, 4096, false, true);
    run_gemm(henc,  wcakvh, nullptr, hcakv, BN*EN, DM, 8192, false, true);

    dim3 flash_grid(QN/128, HN, BN);
    dim3 bd_grid(KLEN/64, QN/128, BN*HN);

    for (int l = 0; l < LNUM; l++) {
        // ---- self-attention (TransformerXL relative) ----
        concat_kernel<<<(BN*KLEN*DM + 255)/256, 256>>>(
            mems + (size_t)l*BN*MN*DM, x, hmem);

        run_gemm(hmem, wqkvh + (size_t)l*3072*DM, nullptr, hqkv,
                 BN*KLEN, DM, 3072, false, true);

        const __half* qself = hqkv + (size_t)MN*3072;
        bd_mma<<<bd_grid, 256>>>(qself, 3072, (size_t)KLEN*3072,
                                 hr4 + (size_t)l*1024, 4096, vpar, bdb);
        flashmma<<<flash_grid, 256, FLASH_SMEM>>>(
            qself, 3072, (size_t)KLEN*3072,
            hqkv + 1024, hqkv + 2048, 3072, (size_t)KLEN*3072,
            bdb, u, hatt, KLEN, 1);

        run_gemm(hatt, wsafch + (size_t)l*DM*DM, safcB + (size_t)l*DM,
                 tmp, BN*QN, DM, DM, false, false);
        ln_kernel<<<BN*QN, 256>>>(x, hxh, tmp, ln1g + (size_t)l*DM, ln1b + (size_t)l*DM);

        // ---- cross-attention ----
        run_gemm(hxh, wcaqh + (size_t)l*DM*DM, nullptr, hq, BN*QN, DM, DM, false, true);

        flashmma<<<flash_grid, 256, FLASH_SMEM>>>(
            hq, DM, (size_t)QN*DM,
            hcakv + (size_t)l*2048, hcakv + (size_t)l*2048 + 1024,
            8192, (size_t)EN*8192,
            nullptr, nullptr, hatt, EN, 0);

        run_gemm(hatt, wcafch + (size_t)l*DM*DM, cafcB + (size_t)l*DM,
                 tmp, BN*QN, DM, DM, false, false);
        ln_kernel<<<BN*QN, 256>>>(x, hxh, tmp, ln2g + (size_t)l*DM, ln2b + (size_t)l*DM);

        // ---- feed-forward ----
        run_gemm(hxh, wff1h + (size_t)l*DM*FFN, ffb1 + (size_t)l*FFN,
                 hff, BN*QN, DM, FFN, true, true);
        run_gemm(hff, wff2h + (size_t)l*DM*FFN, ffb2 + (size_t)l*DM,
                 tmp, BN*QN, FFN, DM, false, false);
        ln_kernel<<<BN*QN, 256>>>(x, hxh, tmp, ln3g + (size_t)l*DM, ln3b + (size_t)l*DM);
    }

    // ---- output projection ----
    run_gemm(hxh, wouth, nullptr, out, BN*QN, DM, VN, false, false);
}

// round 13
// speedup vs baseline: 1.0965x; 1.0242x over previous
#include <cuda_runtime.h>
#include <cuda_fp16.h>
#include <math.h>
#include <stdint.h>

// Problem constants
#define LNUM 4
#define DM   1024
#define HN   16
#define DH   64
#define FFN  4096
#define VN   8192
#define BN   4
#define QN   512
#define MN   512
#define EN   512
#define KLEN 1024   // M + Q

// ---------------- scratch (device globals; no allocation) ----------------
__device__ float  g_x   [BN*QN*DM];         // residual stream (full fp32)
__device__ float  g_tmp [BN*QN*DM];
__device__ float  g_bd  [BN*HN*QN*KLEN];
// half activation buffers
__device__ __half g_hxh  [BN*QN*DM];
__device__ __half g_hmem [BN*KLEN*DM];
__device__ __half g_hqkv [BN*KLEN*3072];
__device__ __half g_hcakv[BN*EN*8192];
__device__ __half g_hr4  [KLEN*4096];
__device__ __half g_hatt [BN*QN*DM];
__device__ __half g_hq   [BN*QN*DM];
__device__ __half g_hff  [BN*QN*FFN];
__device__ __half g_hremb[KLEN*DM];
__device__ __half g_henc [BN*EN*DM];
// transposed half weights (B^T, [n][k] row-major), built per call
__device__ __half g_wqkv [LNUM*3072*DM];
__device__ __half g_wcakv[8192*DM];
__device__ __half g_wr4  [4096*DM];
__device__ __half g_wsafc[LNUM*DM*DM];
__device__ __half g_wcafc[LNUM*DM*DM];
__device__ __half g_wcaq [LNUM*DM*DM];
__device__ __half g_wff1 [LNUM*FFN*DM];
__device__ __half g_wff2 [LNUM*DM*FFN];
__device__ __half g_wout [VN*DM];

// ---------------- helpers ----------------
__device__ __forceinline__ unsigned f2tf(float x) {
    unsigned u; asm("cvt.rna.tf32.f32 %0, %1;" : "=r"(u) : "f"(x)); return u;
}

#define MMA_TF32(C, A, B0, B1)                                                \
    asm volatile(                                                             \
        "mma.sync.aligned.m16n8k8.row.col.f32.tf32.tf32.f32 "                 \
        "{%0,%1,%2,%3}, {%4,%5,%6,%7}, {%8,%9}, {%0,%1,%2,%3};"               \
        : "+f"((C)[0]), "+f"((C)[1]), "+f"((C)[2]), "+f"((C)[3])              \
        : "r"((A)[0]), "r"((A)[1]), "r"((A)[2]), "r"((A)[3]),                 \
          "r"(B0), "r"(B1))

#define MMA_F16(C, A0, A1, A2, A3, B0, B1)                                    \
    asm volatile(                                                             \
        "mma.sync.aligned.m16n8k16.row.col.f32.f16.f16.f32 "                  \
        "{%0,%1,%2,%3}, {%4,%5,%6,%7}, {%8,%9}, {%0,%1,%2,%3};"               \
        : "+f"((C)[0]), "+f"((C)[1]), "+f"((C)[2]), "+f"((C)[3])              \
        : "r"(A0), "r"(A1), "r"(A2), "r"(A3), "r"(B0), "r"(B1))

__device__ __forceinline__ void cp16(uint32_t dst, const void* src) {
    asm volatile("cp.async.cg.shared.global [%0], [%1], 16;\n" :: "r"(dst), "l"(src));
}
#define CP_COMMIT()  asm volatile("cp.async.commit_group;\n" ::)

__device__ __forceinline__ uint32_t smem_u32(const void* p) {
    uint32_t a;
    asm("{ .reg .u64 t; cvta.to.shared.u64 t, %1; cvt.u32.u64 %0, t; }"
        : "=r"(a) : "l"(p));
    return a;
}
__device__ __forceinline__ uint32_t packh2(float a, float b) {
    __half2 h = __floats2half2_rn(a, b);
    return *(uint32_t*)&h;
}

// ---------------- elementwise kernels ----------------
__global__ void half_copy(const float* __restrict__ src,
                          __half* __restrict__ dst, int n4) {
    int i = blockIdx.x * blockDim.x + threadIdx.x;
    if (i >= n4) return;
    float4 v = ((const float4*)src)[i];
    ((__half2*)dst)[2*i]   = __floats2half2_rn(v.x, v.y);
    ((__half2*)dst)[2*i+1] = __floats2half2_rn(v.z, v.w);
}

// transpose + half: src [R, C] fp32 row-major -> dst [C, R] half row-major
__global__ void trans_half(const float* __restrict__ src, __half* __restrict__ dst,
                           int R, int C, size_t sbs, size_t dbs) {
    __shared__ float t[32][33];
    const float* s = src + (size_t)blockIdx.z * sbs;
    __half*      d = dst + (size_t)blockIdx.z * dbs;
    int c0 = blockIdx.x * 32, r0 = blockIdx.y * 32;
    int tx = threadIdx.x, ty = threadIdx.y;
    #pragma unroll
    for (int i = 0; i < 4; i++)
        t[ty + 8*i][tx] = s[(size_t)(r0 + ty + 8*i) * C + c0 + tx];
    __syncthreads();
    #pragma unroll
    for (int i = 0; i < 4; i++)
        d[(size_t)(c0 + ty + 8*i) * R + r0 + tx] = __float2half_rn(t[tx][ty + 8*i]);
}

__global__ void embed_kernel(const int* __restrict__ ids,
                             const float* __restrict__ emb,
                             float* __restrict__ x) {
    int idx = blockIdx.x * blockDim.x + threadIdx.x;
    if (idx >= BN*QN*DM) return;
    int row = idx / DM;
    int d   = idx - row * DM;
    int tok = ids[row];
    x[idx] = emb[tok * DM + d] * 32.0f;
}

__global__ void remb_kernel(__half* __restrict__ remb) {
    int idx = blockIdx.x * blockDim.x + threadIdx.x;
    if (idx >= KLEN*DM) return;
    int p = idx / DM;
    int d = idx - p * DM;
    float pos = (float)(KLEN - 1 - p);
    int k = (d < DM/2) ? d : d - DM/2;
    float invf = powf(10000.0f, -(float)k / (float)(DM/2));
    float a = pos * invf;
    remb[idx] = __float2half_rn((d < DM/2) ? sinf(a) : cosf(a));
}

__global__ void concat_kernel(const float* __restrict__ mems_l,
                              const float* __restrict__ x,
                              __half* __restrict__ mem) {
    int idx = blockIdx.x * blockDim.x + threadIdx.x;
    if (idx >= BN*KLEN*DM) return;
    int d   = idx % DM;
    int rem = idx / DM;
    int j   = rem % KLEN;
    int b   = rem / KLEN;
    float val;
    if (j < MN) val = mems_l[(b*MN + j)*DM + d];
    else        val = x[(b*QN + (j - MN))*DM + d];
    mem[idx] = __float2half_rn(val);
}

// ---------------- fp16 tensor-core GEMM, 4-stage cp.async, 2 CTAs/SM -------
#define STG    4
#define ROWU   12
#define TILE_U (128*ROWU)
#define STAGE_U (2*TILE_U)
#define MM_SMEM (STG*STAGE_U*4)

template<bool GELU, bool HOUT>
__global__ __launch_bounds__(256, 2)
void mm_h(const __half* __restrict__ A, const __half* __restrict__ Bt,
          const float* __restrict__ bias, void* __restrict__ Cout,
          int N, int D, int K) {
    extern __shared__ uint32_t smu[];
    const uint32_t sb = smem_u32(smu);

    const int tid  = threadIdx.x;
    const int row0 = blockIdx.y * 128, col0 = blockIdx.x * 128;
    const int lane = tid & 31, wid = tid >> 5;
    const int grp  = lane >> 2, t4 = lane & 3;
    const int wm   = (wid & 3) * 32, wn = (wid >> 2) * 64;

    const int lrow = tid >> 1;
    const int lseg = tid & 1;
    const __half* Ag = A  + (size_t)(row0 + lrow) * D + lseg * 8;
    const __half* Bg = Bt + (size_t)(col0 + lrow) * D + lseg * 8;
    const uint32_t dstA = sb + (lrow*ROWU + lseg*4) * 4;
    const uint32_t dstB = dstA + TILE_U*4;

    const int KT = D >> 4;

    float c[2][8][4];
    #pragma unroll
    for (int i = 0; i < 2; i++)
        #pragma unroll
        for (int j = 0; j < 8; j++)
            #pragma unroll
            for (int t = 0; t < 4; t++) c[i][j][t] = 0.0f;

    #pragma unroll
    for (int s = 0; s < STG-1; s++) {
        cp16(dstA + s*STAGE_U*4, Ag + (size_t)s*16);
        cp16(dstB + s*STAGE_U*4, Bg + (size_t)s*16);
        CP_COMMIT();
    }

    for (int kt = 0; kt < KT; kt++) {
        asm volatile("cp.async.wait_group 2;\n" ::);
        __syncthreads();
        const int st = kt & (STG-1);
        const uint32_t* AsU = smu + st*STAGE_U;
        const uint32_t* BsU = AsU + TILE_U;

        uint32_t af[2][4], bf[8][2];
        #pragma unroll
        for (int mt = 0; mt < 2; mt++) {
            const int m = wm + mt*16 + grp;
            af[mt][0] = AsU[(m  )*ROWU + t4    ];
            af[mt][1] = AsU[(m+8)*ROWU + t4    ];
            af[mt][2] = AsU[(m  )*ROWU + t4 + 4];
            af[mt][3] = AsU[(m+8)*ROWU + t4 + 4];
        }
        #pragma unroll
        for (int nt = 0; nt < 8; nt++) {
            const int n = wn + nt*8 + grp;
            bf[nt][0] = BsU[n*ROWU + t4    ];
            bf[nt][1] = BsU[n*ROWU + t4 + 4];
        }

        const int kn = kt + STG - 1;
        if (kn < KT) {
            const int sn = kn & (STG-1);
            cp16(dstA + sn*STAGE_U*4, Ag + (size_t)kn*16);
            cp16(dstB + sn*STAGE_U*4, Bg + (size_t)kn*16);
        }
        CP_COMMIT();

        #pragma unroll
        for (int mt = 0; mt < 2; mt++)
            #pragma unroll
            for (int nt = 0; nt < 8; nt++)
                MMA_F16(c[mt][nt], af[mt][0], af[mt][1], af[mt][2], af[mt][3],
                        bf[nt][0], bf[nt][1]);
    }

    #pragma unroll
    for (int mt = 0; mt < 2; mt++)
        #pragma unroll
        for (int nt = 0; nt < 8; nt++) {
            int r  = row0 + wm + mt*16 + grp;
            int cc = col0 + wn + nt*8 + t4*2;
            #pragma unroll
            for (int half = 0; half < 2; half++) {
                int rr = r + half*8;
                float v0 = c[mt][nt][half*2 + 0];
                float v1 = c[mt][nt][half*2 + 1];
                if (bias) { v0 += bias[cc]; v1 += bias[cc+1]; }
                if (GELU) {
                    v0 = 0.5f*v0*(1.0f + erff(v0*0.70710678118654752f));
                    v1 = 0.5f*v1*(1.0f + erff(v1*0.70710678118654752f));
                }
                if (HOUT) {
                    __half* Ch = (__half*)Cout;
                    *(__half2*)&Ch[(size_t)rr*K + cc] = __floats2half2_rn(v0, v1);
                } else {
                    float* Cf = (float*)Cout;
                    *(float2*)&Cf[(size_t)rr*K + cc] = make_float2(v0, v1);
                }
            }
        }
}

// ---------------- BD_raw via fp16 tensor cores ----------------
#define RS_WSTR 36
__global__ __launch_bounds__(256)
void bd_mma(const __half* __restrict__ q, int qrs, size_t qbs,
            const __half* __restrict__ r, int rrs,
            const float* __restrict__ vvec, float* __restrict__ bdout) {
    __shared__ uint32_t RsU[64*RS_WSTR];
    const int t0 = blockIdx.x * 64;
    const int i0 = blockIdx.y * 128;
    const int h = blockIdx.z & (HN-1), b = blockIdx.z >> 4;
    const int tid = threadIdx.x;
    const int lane = tid & 31, wid = tid >> 5;
    const int grp = lane >> 2, t4 = lane & 3;
    const int i_r0 = i0 + wid*16 + grp, i_r1 = i_r0 + 8;

    uint32_t qf[4][4];
    {
        const __half* qp0 = q + (size_t)b*qbs + (size_t)i_r0*qrs + h*DH;
        const __half* qp1 = q + (size_t)b*qbs + (size_t)i_r1*qrs + h*DH;
        const float* up  = vvec + h*DH;
        #pragma unroll
        for (int ks = 0; ks < 4; ks++) {
            int k0 = 16*ks + 2*t4;
            float ua = up[k0], ub = up[k0+1], uc = up[k0+8], ud = up[k0+9];
            qf[ks][0] = packh2(__half2float(qp0[k0])   + ua, __half2float(qp0[k0+1]) + ub);
            qf[ks][1] = packh2(__half2float(qp1[k0])   + ua, __half2float(qp1[k0+1]) + ub);
            qf[ks][2] = packh2(__half2float(qp0[k0+8]) + uc, __half2float(qp0[k0+9]) + ud);
            qf[ks][3] = packh2(__half2float(qp1[k0+8]) + uc, __half2float(qp1[k0+9]) + ud);
        }
    }
    #pragma unroll
    for (int t = 0; t < 2; t++) {
        int idx = tid + 256*t;
        int row = idx >> 3, c8 = (idx & 7) * 8;
        uint4 rv = *(const uint4*)&r[(size_t)(t0 + row)*rrs + h*DH + c8];
        *(uint4*)&RsU[row*RS_WSTR + (idx & 7)*4] = rv;
    }
    __syncthreads();

    float s[8][4];
    #pragma unroll
    for (int nt = 0; nt < 8; nt++)
        #pragma unroll
        for (int e = 0; e < 4; e++) s[nt][e] = 0.0f;

    #pragma unroll
    for (int ks = 0; ks < 4; ks++)
        #pragma unroll
        for (int nt = 0; nt < 8; nt++) {
            uint32_t b0 = RsU[(nt*8+grp)*RS_WSTR + t4 + 8*ks];
            uint32_t b1 = RsU[(nt*8+grp)*RS_WSTR + t4 + 4 + 8*ks];
            MMA_F16(s[nt], qf[ks][0], qf[ks][1], qf[ks][2], qf[ks][3], b0, b1);
        }

    float* o0 = bdout + (((size_t)(b*HN + h))*QN + i_r0)*KLEN + t0;
    float* o1 = bdout + (((size_t)(b*HN + h))*QN + i_r1)*KLEN + t0;
    #pragma unroll
    for (int nt = 0; nt < 8; nt++) {
        int cc = nt*8 + 2*t4;
        *(float2*)&o0[cc] = make_float2(s[nt][0], s[nt][1]);
        *(float2*)&o1[cc] = make_float2(s[nt][2], s[nt][3]);
    }
}

// ------- MMA flash attention: cp.async double-buffered K/V, fp16 QK, tf32 PV
// smem word layout: Kst[2][64*36] | Vst[2][64*36] | Vsf float[64*72] | Ps float[128*68]
#define F_KST 0
#define F_VST 4608
#define F_VSF 9216
#define F_PS  13824
#define F_BUF 2304
#define VS_STRIDE 72
#define PS_STRIDE 68
#define FLASH_SMEM ((13824 + 8704)*4)

__global__ __launch_bounds__(256)
void flashmma(const __half* __restrict__ q, int qrs, size_t qbs,
              const __half* __restrict__ k, const __half* __restrict__ v,
              int kvrs, size_t kvbs,
              const float* __restrict__ bd, const float* __restrict__ uvec,
              __half* __restrict__ out, int klen, int useMask) {
    extern __shared__ uint32_t smu[];
    const uint32_t sb = smem_u32(smu);
    float* Vsf = (float*)(smu + F_VSF);
    float* Ps  = (float*)(smu + F_PS);

    const int i0 = blockIdx.x * 128;
    const int h = blockIdx.y, b = blockIdx.z;
    const int tid = threadIdx.x;
    const int lane = tid & 31, wid = tid >> 5;
    const int grp = lane >> 2, t4 = lane & 3;
    const int r0 = wid*16 + grp, r1 = r0 + 8;
    const int i_r0 = i0 + r0, i_r1 = i0 + r1;

    uint32_t qf[4][4];
    {
        const __half* qp0 = q + (size_t)b*qbs + (size_t)i_r0*qrs + h*DH;
        const __half* qp1 = q + (size_t)b*qbs + (size_t)i_r1*qrs + h*DH;
        #pragma unroll
        for (int ks = 0; ks < 4; ks++) {
            int k0 = 16*ks + 2*t4;
            float ua = uvec ? uvec[h*DH + k0]   : 0.0f;
            float ub = uvec ? uvec[h*DH + k0+1] : 0.0f;
            float uc = uvec ? uvec[h*DH + k0+8] : 0.0f;
            float ud = uvec ? uvec[h*DH + k0+9] : 0.0f;
            qf[ks][0] = packh2(__half2float(qp0[k0])   + ua, __half2float(qp0[k0+1]) + ub);
            qf[ks][1] = packh2(__half2float(qp1[k0])   + ua, __half2float(qp1[k0+1]) + ub);
            qf[ks][2] = packh2(__half2float(qp0[k0+8]) + uc, __half2float(qp0[k0+9]) + ud);
            qf[ks][3] = packh2(__half2float(qp1[k0+8]) + uc, __half2float(qp1[k0+9]) + ud);
        }
    }

    float m0 = -INFINITY, m1 = -INFINITY, l0 = 0.0f, l1 = 0.0f;
    float o[8][4];
    #pragma unroll
    for (int nt = 0; nt < 8; nt++)
        #pragma unroll
        for (int e = 0; e < 4; e++) o[nt][e] = 0.0f;

    const float* bdr0 = bd ? bd + (((size_t)(b*HN + h))*QN + i_r0)*KLEN : (const float*)0;
    const float* bdr1 = bd ? bd + (((size_t)(b*HN + h))*QN + i_r1)*KLEN : (const float*)0;

    int lastj = klen - 1;
    if (useMask) { int lm = i0 + 127 + MN; if (lm < lastj) lastj = lm; }
    const int nch = lastj/64 + 1;

    // loader mapping: thread -> rows lrow0, lrow0+32 ; 16B segment lseg
    const int lrow0 = tid >> 3, lseg = tid & 7;
    const __half* kbase = k + (size_t)b*kvbs + h*DH + lseg*8;
    const __half* vbase = v + (size_t)b*kvbs + h*DH + lseg*8;

    // prologue: issue chunk 0
    {
        #pragma unroll
        for (int t = 0; t < 2; t++) {
            int row = lrow0 + 32*t;
            cp16(sb + (F_KST + row*36 + lseg*4)*4, kbase + (size_t)row*kvrs);
            cp16(sb + (F_VST + row*36 + lseg*4)*4, vbase + (size_t)row*kvrs);
        }
        CP_COMMIT();
    }

    for (int c = 0; c < nch; c++) {
        const int j0 = c*64;
        // prefetch chunk c+1
        if (c + 1 < nch) {
            const int bn = (c+1) & 1;
            const int jn = (c+1)*64;
            #pragma unroll
            for (int t = 0; t < 2; t++) {
                int row = lrow0 + 32*t;
                cp16(sb + (F_KST + bn*F_BUF + row*36 + lseg*4)*4,
                     kbase + (size_t)(jn + row)*kvrs);
                cp16(sb + (F_VST + bn*F_BUF + row*36 + lseg*4)*4,
                     vbase + (size_t)(jn + row)*kvrs);
            }
        }
        CP_COMMIT();
        asm volatile("cp.async.wait_group 1;\n" ::);
        __syncthreads();

        // convert V staging (half) -> Vsf (float)
        {
            const uint32_t* Vst = smu + F_VST + (c & 1)*F_BUF;
            #pragma unroll
            for (int t = 0; t < 2; t++) {
                int row = lrow0 + 32*t;
                uint4 vv = *(const uint4*)&Vst[row*36 + lseg*4];
                float* vd = Vsf + row*VS_STRIDE + lseg*8;
                float2 f0 = __half22float2(*(__half2*)&vv.x);
                float2 f1 = __half22float2(*((__half2*)&vv.x + 1));
                float2 f2 = __half22float2(*(__half2*)&vv.z);
                float2 f3 = __half22float2(*((__half2*)&vv.z + 1));
                vd[0]=f0.x; vd[1]=f0.y; vd[2]=f1.x; vd[3]=f1.y;
                vd[4]=f2.x; vd[5]=f2.y; vd[6]=f3.x; vd[7]=f3.y;
            }
        }
        __syncthreads();

        const uint32_t* KsU = smu + F_KST + (c & 1)*F_BUF;

        float bdv[8][4];
        if (bd) {
            #pragma unroll
            for (int nt = 0; nt < 8; nt++) {
                int jA = j0 + nt*8 + 2*t4;
                int jr0 = jA - i_r0 + (QN-1);
                int jr1 = jA - i_r1 + (QN-1);
                jr0 = max(0, min(KLEN-2, jr0));
                jr1 = max(0, min(KLEN-2, jr1));
                bdv[nt][0] = bdr0[jr0];   bdv[nt][1] = bdr0[jr0+1];
                bdv[nt][2] = bdr1[jr1];   bdv[nt][3] = bdr1[jr1+1];
            }
        }

        // S = Q @ K^T  (fp16)
        float s[8][4];
        #pragma unroll
        for (int nt = 0; nt < 8; nt++)
            #pragma unroll
            for (int e = 0; e < 4; e++) s[nt][e] = 0.0f;
        #pragma unroll
        for (int ks = 0; ks < 4; ks++)
            #pragma unroll
            for (int nt = 0; nt < 8; nt++) {
                uint32_t b0 = KsU[(nt*8+grp)*36 + t4 + 8*ks];
                uint32_t b1 = KsU[(nt*8+grp)*36 + t4 + 4 + 8*ks];
                MMA_F16(s[nt], qf[ks][0], qf[ks][1], qf[ks][2], qf[ks][3], b0, b1);
            }

        float mc0 = -INFINITY, mc1 = -INFINITY;
        #pragma unroll
        for (int nt = 0; nt < 8; nt++) {
            int jA = j0 + nt*8 + 2*t4;
            int jB = jA + 1;
            float v0 = s[nt][0], v1 = s[nt][1], v2 = s[nt][2], v3 = s[nt][3];
            if (bd) { v0 += bdv[nt][0]; v1 += bdv[nt][1]; v2 += bdv[nt][2]; v3 += bdv[nt][3]; }
            v0 *= 0.125f; v1 *= 0.125f; v2 *= 0.125f; v3 *= 0.125f;
            if (useMask) {
                if (jA > i_r0 + MN) v0 = -INFINITY;
                if (jB > i_r0 + MN) v1 = -INFINITY;
                if (jA > i_r1 + MN) v2 = -INFINITY;
                if (jB > i_r1 + MN) v3 = -INFINITY;
            }
            s[nt][0]=v0; s[nt][1]=v1; s[nt][2]=v2; s[nt][3]=v3;
            mc0 = fmaxf(mc0, fmaxf(v0, v1));
            mc1 = fmaxf(mc1, fmaxf(v2, v3));
        }
        mc0 = fmaxf(mc0, __shfl_xor_sync(0xffffffffu, mc0, 1));
        mc0 = fmaxf(mc0, __shfl_xor_sync(0xffffffffu, mc0, 2));
        mc1 = fmaxf(mc1, __shfl_xor_sync(0xffffffffu, mc1, 1));
        mc1 = fmaxf(mc1, __shfl_xor_sync(0xffffffffu, mc1, 2));

        float nm0 = fmaxf(m0, mc0), nm1 = fmaxf(m1, mc1);
        float corr0 = __expf(m0 - nm0), corr1 = __expf(m1 - nm1);
        float ps0 = 0.0f, ps1 = 0.0f;
        #pragma unroll
        for (int nt = 0; nt < 8; nt++) {
            float p0 = __expf(s[nt][0] - nm0);
            float p1 = __expf(s[nt][1] - nm0);
            float p2 = __expf(s[nt][2] - nm1);
            float p3 = __expf(s[nt][3] - nm1);
            ps0 += p0 + p1; ps1 += p2 + p3;
            int cc = nt*8 + 2*t4;
            Ps[r0*PS_STRIDE + cc]     = __uint_as_float(f2tf(p0));
            Ps[r0*PS_STRIDE + cc + 1] = __uint_as_float(f2tf(p1));
            Ps[r1*PS_STRIDE + cc]     = __uint_as_float(f2tf(p2));
            Ps[r1*PS_STRIDE + cc + 1] = __uint_as_float(f2tf(p3));
        }
        ps0 += __shfl_xor_sync(0xffffffffu, ps0, 1);
        ps0 += __shfl_xor_sync(0xffffffffu, ps0, 2);
        ps1 += __shfl_xor_sync(0xffffffffu, ps1, 1);
        ps1 += __shfl_xor_sync(0xffffffffu, ps1, 2);
        l0 = l0 * corr0 + ps0;  m0 = nm0;
        l1 = l1 * corr1 + ps1;  m1 = nm1;
        #pragma unroll
        for (int nt = 0; nt < 8; nt++) {
            o[nt][0] *= corr0; o[nt][1] *= corr0;
            o[nt][2] *= corr1; o[nt][3] *= corr1;
        }
        __syncwarp();

        // O += P @ V  (tf32)
        #pragma unroll
        for (int ks = 0; ks < 8; ks++) {
            unsigned a[4];
            a[0] = __float_as_uint(Ps[r0*PS_STRIDE + ks*8 + t4]);
            a[1] = __float_as_uint(Ps[r1*PS_STRIDE + ks*8 + t4]);
            a[2] = __float_as_uint(Ps[r0*PS_STRIDE + ks*8 + t4 + 4]);
            a[3] = __float_as_uint(Ps[r1*PS_STRIDE + ks*8 + t4 + 4]);
            #pragma unroll
            for (int nt = 0; nt < 8; nt++) {
                unsigned b0 = __float_as_uint(Vsf[(ks*8+t4)*VS_STRIDE + nt*8 + grp]);
                unsigned b1 = __float_as_uint(Vsf[(ks*8+t4+4)*VS_STRIDE + nt*8 + grp]);
                MMA_TF32(o[nt], a, b0, b1);
            }
        }
        __syncthreads();   // protect staging buffers before next iteration's issue
    }

    const float inv0 = 1.0f / l0, inv1 = 1.0f / l1;
    __half* op0 = out + ((size_t)(b*QN + i_r0))*DM + h*DH;
    __half* op1 = out + ((size_t)(b*QN + i_r1))*DM + h*DH;
    #pragma unroll
    for (int nt = 0; nt < 8; nt++) {
        int cc = nt*8 + 2*t4;
        *(__half2*)&op0[cc] = __floats2half2_rn(o[nt][0]*inv0, o[nt][1]*inv0);
        *(__half2*)&op1[cc] = __floats2half2_rn(o[nt][2]*inv1, o[nt][3]*inv1);
    }
}

// ------- residual add + LayerNorm (single-pass shuffle reduction) ----------
__global__ __launch_bounds__(256)
void ln_kernel(float* __restrict__ x, __half* __restrict__ xh,
               const float* __restrict__ y,
               const float* __restrict__ gamma, const float* __restrict__ beta) {
    const int row = blockIdx.x;
    const int tid = threadIdx.x;
    const int lane = tid & 31, wid = tid >> 5;
    __shared__ float rs[8], rq[8];

    float s[4];
    float sum = 0.0f, sq = 0.0f;
    #pragma unroll
    for (int kk = 0; kk < 4; kk++) {
        int c = tid + kk*256;
        float val = x[(size_t)row*DM + c] + y[(size_t)row*DM + c];
        s[kk] = val;
        sum += val;
        sq  = fmaf(val, val, sq);
    }
    #pragma unroll
    for (int d = 16; d > 0; d >>= 1) {
        sum += __shfl_xor_sync(0xffffffffu, sum, d);
        sq  += __shfl_xor_sync(0xffffffffu, sq,  d);
    }
    if (lane == 0) { rs[wid] = sum; rq[wid] = sq; }
    __syncthreads();
    float tot = 0.0f, totq = 0.0f;
    #pragma unroll
    for (int w = 0; w < 8; w++) { tot += rs[w]; totq += rq[w]; }
    const float mu = tot * (1.0f / DM);
    const float var = totq * (1.0f / DM) - mu * mu;
    const float rstd = rsqrtf(var + 1e-5f);

    #pragma unroll
    for (int kk = 0; kk < 4; kk++) {
        int c = tid + kk*256;
        float val = (s[kk] - mu) * rstd * gamma[c] + beta[c];
        x [(size_t)row*DM + c] = val;
        xh[(size_t)row*DM + c] = __float2half_rn(val);
    }
}

// ---------------- host orchestration ----------------
static inline void run_gemm(const __half* A, const __half* Bt, const float* bias,
                            void* C, int N, int D, int K, bool gelu, bool hout) {
    dim3 grid(K/128, N/128);
    if (gelu)      mm_h<true , true ><<<grid, 256, MM_SMEM>>>(A, Bt, bias, C, N, D, K);
    else if (hout) mm_h<false, true ><<<grid, 256, MM_SMEM>>>(A, Bt, bias, C, N, D, K);
    else           mm_h<false, false><<<grid, 256, MM_SMEM>>>(A, Bt, bias, C, N, D, K);
}

extern "C" void kernel_launch(void* const* d_in, const int* in_sizes, int n_in,
                              void* d_out, int out_size) {
    const float* enc    = (const float*)d_in[0];
    const float* mems   = (const float*)d_in[1];
    const float* emb    = (const float*)d_in[2];
    const float* u      = (const float*)d_in[3];
    const float* vpar   = (const float*)d_in[4];
    const float* saWq   = (const float*)d_in[5];
    const float* saWk   = (const float*)d_in[6];
    const float* saWv   = (const float*)d_in[7];
    const float* saWr   = (const float*)d_in[8];
    const float* safcW  = (const float*)d_in[9];
    const float* safcB  = (const float*)d_in[10];
    const float* ln1g   = (const float*)d_in[11];
    const float* ln1b   = (const float*)d_in[12];
    const float* caWq   = (const float*)d_in[13];
    const float* caWk   = (const float*)d_in[14];
    const float* caWv   = (const float*)d_in[15];
    const float* cafcW  = (const float*)d_in[16];
    const float* cafcB  = (const float*)d_in[17];
    const float* ln2g   = (const float*)d_in[18];
    const float* ln2b   = (const float*)d_in[19];
    const float* ffW1   = (const float*)d_in[20];
    const float* ffb1   = (const float*)d_in[21];
    const float* ffW2   = (const float*)d_in[22];
    const float* ffb2   = (const float*)d_in[23];
    const float* ln3g   = (const float*)d_in[24];
    const float* ln3b   = (const float*)d_in[25];
    const float* outW   = (const float*)d_in[26];
    const int*   ids    = (const int*)  d_in[27];
    float* out = (float*)d_out;

    float *x, *tmp, *bdb;
    __half *hxh, *hmem, *hqkv, *hcakv, *hr4, *hatt, *hq, *hff, *hremb, *henc;
    __half *wqkvh, *wcakvh, *wr4h, *wsafch, *wcafch, *wcaqh, *wff1h, *wff2h, *wouth;
    cudaGetSymbolAddress((void**)&x,      g_x);
    cudaGetSymbolAddress((void**)&tmp,    g_tmp);
    cudaGetSymbolAddress((void**)&bdb,    g_bd);
    cudaGetSymbolAddress((void**)&hxh,    g_hxh);
    cudaGetSymbolAddress((void**)&hmem,   g_hmem);
    cudaGetSymbolAddress((void**)&hqkv,   g_hqkv);
    cudaGetSymbolAddress((void**)&hcakv,  g_hcakv);
    cudaGetSymbolAddress((void**)&hr4,    g_hr4);
    cudaGetSymbolAddress((void**)&hatt,   g_hatt);
    cudaGetSymbolAddress((void**)&hq,     g_hq);
    cudaGetSymbolAddress((void**)&hff,    g_hff);
    cudaGetSymbolAddress((void**)&hremb,  g_hremb);
    cudaGetSymbolAddress((void**)&henc,   g_henc);
    cudaGetSymbolAddress((void**)&wqkvh,  g_wqkv);
    cudaGetSymbolAddress((void**)&wcakvh, g_wcakv);
    cudaGetSymbolAddress((void**)&wr4h,   g_wr4);
    cudaGetSymbolAddress((void**)&wsafch, g_wsafc);
    cudaGetSymbolAddress((void**)&wcafch, g_wcafc);
    cudaGetSymbolAddress((void**)&wcaqh,  g_wcaq);
    cudaGetSymbolAddress((void**)&wff1h,  g_wff1);
    cudaGetSymbolAddress((void**)&wff2h,  g_wff2);
    cudaGetSymbolAddress((void**)&wouth,  g_wout);

    static int smem_set = 0;
    if (!smem_set) {
        cudaFuncSetAttribute(flashmma, cudaFuncAttributeMaxDynamicSharedMemorySize,
                             FLASH_SMEM);
        cudaFuncSetAttribute((mm_h<true , true >), cudaFuncAttributeMaxDynamicSharedMemorySize, MM_SMEM);
        cudaFuncSetAttribute((mm_h<false, true >), cudaFuncAttributeMaxDynamicSharedMemorySize, MM_SMEM);
        cudaFuncSetAttribute((mm_h<false, false>), cudaFuncAttributeMaxDynamicSharedMemorySize, MM_SMEM);
        smem_set = 1;
    }

    // transposed half weights (Bt = W^T, [n][k] row-major)
    dim3 tb(32, 8);
    trans_half<<<dim3(DM/32, DM/32, LNUM), tb>>>(saWq, wqkvh,                   DM, DM, (size_t)DM*DM, (size_t)3072*DM);
    trans_half<<<dim3(DM/32, DM/32, LNUM), tb>>>(saWk, wqkvh + (size_t)1024*DM, DM, DM, (size_t)DM*DM, (size_t)3072*DM);
    trans_half<<<dim3(DM/32, DM/32, LNUM), tb>>>(saWv, wqkvh + (size_t)2048*DM, DM, DM, (size_t)DM*DM, (size_t)3072*DM);
    trans_half<<<dim3(DM/32, DM/32, LNUM), tb>>>(caWk, wcakvh,                  DM, DM, (size_t)DM*DM, (size_t)2048*DM);
    trans_half<<<dim3(DM/32, DM/32, LNUM), tb>>>(caWv, wcakvh + (size_t)1024*DM,DM, DM, (size_t)DM*DM, (size_t)2048*DM);
    trans_half<<<dim3(DM/32, DM/32, LNUM), tb>>>(saWr,  wr4h,   DM, DM, (size_t)DM*DM, (size_t)DM*DM);
    trans_half<<<dim3(DM/32, DM/32, LNUM), tb>>>(safcW, wsafch, DM, DM, (size_t)DM*DM, (size_t)DM*DM);
    trans_half<<<dim3(DM/32, DM/32, LNUM), tb>>>(cafcW, wcafch, DM, DM, (size_t)DM*DM, (size_t)DM*DM);
    trans_half<<<dim3(DM/32, DM/32, LNUM), tb>>>(caWq,  wcaqh,  DM, DM, (size_t)DM*DM, (size_t)DM*DM);
    trans_half<<<dim3(FFN/32, DM/32, LNUM), tb>>>(ffW1, wff1h,  DM, FFN, (size_t)DM*FFN, (size_t)DM*FFN);
    trans_half<<<dim3(DM/32, FFN/32, LNUM), tb>>>(ffW2, wff2h,  FFN, DM, (size_t)DM*FFN, (size_t)DM*FFN);
    trans_half<<<dim3(VN/32, DM/32, 1),     tb>>>(outW, wouth,  DM, VN, 0, 0);
    half_copy<<<((BN*EN*DM/4) + 255)/256, 256>>>(enc, henc, BN*EN*DM/4);

    embed_kernel<<<(BN*QN*DM + 255)/256, 256>>>(ids, emb, x);
    remb_kernel <<<(KLEN*DM + 255)/256, 256>>>(hremb);

    // layer-independent projections (fused across layers)
    run_gemm(hremb, wr4h,   nullptr, hr4,   KLEN,  DM, 4096, false, true);
    run_gemm(henc,  wcakvh, nullptr, hcakv, BN*EN, DM, 8192, false, true);

    dim3 flash_grid(QN/128, HN, BN);
    dim3 bd_grid(KLEN/64, QN/128, BN*HN);

    for (int l = 0; l < LNUM; l++) {
        // ---- self-attention (TransformerXL relative) ----
        concat_kernel<<<(BN*KLEN*DM + 255)/256, 256>>>(
            mems + (size_t)l*BN*MN*DM, x, hmem);

        run_gemm(hmem, wqkvh + (size_t)l*3072*DM, nullptr, hqkv,
                 BN*KLEN, DM, 3072, false, true);

        const __half* qself = hqkv + (size_t)MN*3072;
        bd_mma<<<bd_grid, 256>>>(qself, 3072, (size_t)KLEN*3072,
                                 hr4 + (size_t)l*1024, 4096, vpar, bdb);
        flashmma<<<flash_grid, 256, FLASH_SMEM>>>(
            qself, 3072, (size_t)KLEN*3072,
            hqkv + 1024, hqkv + 2048, 3072, (size_t)KLEN*3072,
            bdb, u, hatt, KLEN, 1);

        run_gemm(hatt, wsafch + (size_t)l*DM*DM, safcB + (size_t)l*DM,
                 tmp, BN*QN, DM, DM, false, false);
        ln_kernel<<<BN*QN, 256>>>(x, hxh, tmp, ln1g + (size_t)l*DM, ln1b + (size_t)l*DM);

        // ---- cross-attention ----
        run_gemm(hxh, wcaqh + (size_t)l*DM*DM, nullptr, hq, BN*QN, DM, DM, false, true);

        flashmma<<<flash_grid, 256, FLASH_SMEM>>>(
            hq, DM, (size_t)QN*DM,
            hcakv + (size_t)l*2048, hcakv + (size_t)l*2048 + 1024,
            8192, (size_t)EN*8192,
            nullptr, nullptr, hatt, EN, 0);

        run_gemm(hatt, wcafch + (size_t)l*DM*DM, cafcB + (size_t)l*DM,
                 tmp, BN*QN, DM, DM, false, false);
        ln_kernel<<<BN*QN, 256>>>(x, hxh, tmp, ln2g + (size_t)l*DM, ln2b + (size_t)l*DM);

        // ---- feed-forward ----
        run_gemm(hxh, wff1h + (size_t)l*DM*FFN, ffb1 + (size_t)l*FFN,
                 hff, BN*QN, DM, FFN, true, true);
        run_gemm(hff, wff2h + (size_t)l*DM*FFN, ffb2 + (size_t)l*DM,
                 tmp, BN*QN, FFN, DM, false, false);
        ln_kernel<<<BN*QN, 256>>>(x, hxh, tmp, ln3g + (size_t)l*DM, ln3b + (size_t)l*DM);
    }

    // ---- output projection ----
    run_gemm(hxh, wouth, nullptr, out, BN*QN, DM, VN, false, false);
}

// round 14
// speedup vs baseline: 1.1895x; 1.0848x over previous
#include <cuda_runtime.h>
#include <cuda_fp16.h>
#include <math.h>
#include <stdint.h>

// Problem constants
#define LNUM 4
#define DM   1024
#define HN   16
#define DH   64
#define FFN  4096
#define VN   8192
#define BN   4
#define QN   512
#define MN   512
#define EN   512
#define KLEN 1024   // M + Q

// ---------------- scratch (device globals; no allocation) ----------------
__device__ float  g_x   [BN*QN*DM];         // residual stream (full fp32)
__device__ float  g_tmp [BN*QN*DM];
__device__ float  g_bd  [BN*HN*QN*KLEN];
// half activation buffers
__device__ __half g_hxh  [BN*QN*DM];
__device__ __half g_hmem [BN*KLEN*DM];
__device__ __half g_hqkv [BN*KLEN*3072];
__device__ __half g_hcakv[BN*EN*8192];
__device__ __half g_hr4  [KLEN*4096];
__device__ __half g_hatt [BN*QN*DM];
__device__ __half g_hq   [BN*QN*DM];
__device__ __half g_hff  [BN*QN*FFN];
__device__ __half g_hremb[KLEN*DM];
__device__ __half g_henc [BN*EN*DM];
// transposed half weights (B^T, [n][k] row-major), built per call
__device__ __half g_wqkv [LNUM*3072*DM];
__device__ __half g_wcakv[8192*DM];
__device__ __half g_wr4  [4096*DM];
__device__ __half g_wsafc[LNUM*DM*DM];
__device__ __half g_wcafc[LNUM*DM*DM];
__device__ __half g_wcaq [LNUM*DM*DM];
__device__ __half g_wff1 [LNUM*FFN*DM];
__device__ __half g_wff2 [LNUM*DM*FFN];
__device__ __half g_wout [VN*DM];

// ---------------- helpers ----------------
#define MMA_F16(C, A0, A1, A2, A3, B0, B1)                                    \
    asm volatile(                                                             \
        "mma.sync.aligned.m16n8k16.row.col.f32.f16.f16.f32 "                  \
        "{%0,%1,%2,%3}, {%4,%5,%6,%7}, {%8,%9}, {%0,%1,%2,%3};"               \
        : "+f"((C)[0]), "+f"((C)[1]), "+f"((C)[2]), "+f"((C)[3])              \
        : "r"(A0), "r"(A1), "r"(A2), "r"(A3), "r"(B0), "r"(B1))

__device__ __forceinline__ void cp16(uint32_t dst, const void* src) {
    asm volatile("cp.async.cg.shared.global [%0], [%1], 16;\n" :: "r"(dst), "l"(src));
}
#define CP_COMMIT()  asm volatile("cp.async.commit_group;\n" ::)

__device__ __forceinline__ uint32_t smem_u32(const void* p) {
    uint32_t a;
    asm("{ .reg .u64 t; cvta.to.shared.u64 t, %1; cvt.u32.u64 %0, t; }"
        : "=r"(a) : "l"(p));
    return a;
}
__device__ __forceinline__ uint32_t packh2(float a, float b) {
    __half2 h = __floats2half2_rn(a, b);
    return *(uint32_t*)&h;
}

// ---------------- elementwise kernels ----------------
__global__ void half_copy(const float* __restrict__ src,
                          __half* __restrict__ dst, int n4) {
    int i = blockIdx.x * blockDim.x + threadIdx.x;
    if (i >= n4) return;
    float4 v = ((const float4*)src)[i];
    ((__half2*)dst)[2*i]   = __floats2half2_rn(v.x, v.y);
    ((__half2*)dst)[2*i+1] = __floats2half2_rn(v.z, v.w);
}

// transpose + half: src [R, C] fp32 row-major -> dst [C, R] half row-major
__global__ void trans_half(const float* __restrict__ src, __half* __restrict__ dst,
                           int R, int C, size_t sbs, size_t dbs) {
    __shared__ float t[32][33];
    const float* s = src + (size_t)blockIdx.z * sbs;
    __half*      d = dst + (size_t)blockIdx.z * dbs;
    int c0 = blockIdx.x * 32, r0 = blockIdx.y * 32;
    int tx = threadIdx.x, ty = threadIdx.y;
    #pragma unroll
    for (int i = 0; i < 4; i++)
        t[ty + 8*i][tx] = s[(size_t)(r0 + ty + 8*i) * C + c0 + tx];
    __syncthreads();
    #pragma unroll
    for (int i = 0; i < 4; i++)
        d[(size_t)(c0 + ty + 8*i) * R + r0 + tx] = __float2half_rn(t[tx][ty + 8*i]);
}

// batched DM x DM transpose+convert: 9 weight groups x LNUM layers, one launch
struct TB9 {
    const float* s[9];
    __half*      d[9];
    unsigned long long dbs[9];
};
__global__ void trans_half9(TB9 tb) {
    __shared__ float t[32][33];
    const int idx = blockIdx.z >> 2;          // /LNUM (LNUM==4)
    const int l   = blockIdx.z & 3;
    const float* s = tb.s[idx] + (size_t)l * DM * DM;
    __half*      d = tb.d[idx] + (size_t)l * tb.dbs[idx];
    int c0 = blockIdx.x * 32, r0 = blockIdx.y * 32;
    int tx = threadIdx.x, ty = threadIdx.y;
    #pragma unroll
    for (int i = 0; i < 4; i++)
        t[ty + 8*i][tx] = s[(size_t)(r0 + ty + 8*i) * DM + c0 + tx];
    __syncthreads();
    #pragma unroll
    for (int i = 0; i < 4; i++)
        d[(size_t)(c0 + ty + 8*i) * DM + r0 + tx] = __float2half_rn(t[tx][ty + 8*i]);
}

__global__ void embed_kernel(const int* __restrict__ ids,
                             const float* __restrict__ emb,
                             float* __restrict__ x) {
    int idx = blockIdx.x * blockDim.x + threadIdx.x;
    if (idx >= BN*QN*DM) return;
    int row = idx / DM;
    int d   = idx - row * DM;
    int tok = ids[row];
    x[idx] = emb[tok * DM + d] * 32.0f;
}

__global__ void remb_kernel(__half* __restrict__ remb) {
    int idx = blockIdx.x * blockDim.x + threadIdx.x;
    if (idx >= KLEN*DM) return;
    int p = idx / DM;
    int d = idx - p * DM;
    float pos = (float)(KLEN - 1 - p);
    int k = (d < DM/2) ? d : d - DM/2;
    float invf = powf(10000.0f, -(float)k / (float)(DM/2));
    float a = pos * invf;
    remb[idx] = __float2half_rn((d < DM/2) ? sinf(a) : cosf(a));
}

__global__ void concat_kernel(const float* __restrict__ mems_l,
                              const float* __restrict__ x,
                              __half* __restrict__ mem) {
    int idx = blockIdx.x * blockDim.x + threadIdx.x;
    if (idx >= BN*KLEN*DM) return;
    int d   = idx % DM;
    int rem = idx / DM;
    int j   = rem % KLEN;
    int b   = rem / KLEN;
    float val;
    if (j < MN) val = mems_l[(b*MN + j)*DM + d];
    else        val = x[(b*QN + (j - MN))*DM + d];
    mem[idx] = __float2half_rn(val);
}

// ---------------- fp16 tensor-core GEMM, 4-stage cp.async, 2 CTAs/SM -------
#define STG    4
#define ROWU   12
#define TILE_U (128*ROWU)
#define STAGE_U (2*TILE_U)
#define MM_SMEM (STG*STAGE_U*4)

template<bool GELU, bool HOUT>
__global__ __launch_bounds__(256, 2)
void mm_h(const __half* __restrict__ A, const __half* __restrict__ Bt,
          const float* __restrict__ bias, void* __restrict__ Cout,
          int N, int D, int K) {
    extern __shared__ uint32_t smu[];
    const uint32_t sb = smem_u32(smu);

    const int tid  = threadIdx.x;
    const int row0 = blockIdx.y * 128, col0 = blockIdx.x * 128;
    const int lane = tid & 31, wid = tid >> 5;
    const int grp  = lane >> 2, t4 = lane & 3;
    const int wm   = (wid & 3) * 32, wn = (wid >> 2) * 64;

    const int lrow = tid >> 1;
    const int lseg = tid & 1;
    const __half* Ag = A  + (size_t)(row0 + lrow) * D + lseg * 8;
    const __half* Bg = Bt + (size_t)(col0 + lrow) * D + lseg * 8;
    const uint32_t dstA = sb + (lrow*ROWU + lseg*4) * 4;
    const uint32_t dstB = dstA + TILE_U*4;

    const int KT = D >> 4;

    float c[2][8][4];
    #pragma unroll
    for (int i = 0; i < 2; i++)
        #pragma unroll
        for (int j = 0; j < 8; j++)
            #pragma unroll
            for (int t = 0; t < 4; t++) c[i][j][t] = 0.0f;

    #pragma unroll
    for (int s = 0; s < STG-1; s++) {
        cp16(dstA + s*STAGE_U*4, Ag + (size_t)s*16);
        cp16(dstB + s*STAGE_U*4, Bg + (size_t)s*16);
        CP_COMMIT();
    }

    for (int kt = 0; kt < KT; kt++) {
        asm volatile("cp.async.wait_group 2;\n" ::);
        __syncthreads();
        const int st = kt & (STG-1);
        const uint32_t* AsU = smu + st*STAGE_U;
        const uint32_t* BsU = AsU + TILE_U;

        uint32_t af[2][4], bf[8][2];
        #pragma unroll
        for (int mt = 0; mt < 2; mt++) {
            const int m = wm + mt*16 + grp;
            af[mt][0] = AsU[(m  )*ROWU + t4    ];
            af[mt][1] = AsU[(m+8)*ROWU + t4    ];
            af[mt][2] = AsU[(m  )*ROWU + t4 + 4];
            af[mt][3] = AsU[(m+8)*ROWU + t4 + 4];
        }
        #pragma unroll
        for (int nt = 0; nt < 8; nt++) {
            const int n = wn + nt*8 + grp;
            bf[nt][0] = BsU[n*ROWU + t4    ];
            bf[nt][1] = BsU[n*ROWU + t4 + 4];
        }

        const int kn = kt + STG - 1;
        if (kn < KT) {
            const int sn = kn & (STG-1);
            cp16(dstA + sn*STAGE_U*4, Ag + (size_t)kn*16);
            cp16(dstB + sn*STAGE_U*4, Bg + (size_t)kn*16);
        }
        CP_COMMIT();

        #pragma unroll
        for (int mt = 0; mt < 2; mt++)
            #pragma unroll
            for (int nt = 0; nt < 8; nt++)
                MMA_F16(c[mt][nt], af[mt][0], af[mt][1], af[mt][2], af[mt][3],
                        bf[nt][0], bf[nt][1]);
    }

    #pragma unroll
    for (int mt = 0; mt < 2; mt++)
        #pragma unroll
        for (int nt = 0; nt < 8; nt++) {
            int r  = row0 + wm + mt*16 + grp;
            int cc = col0 + wn + nt*8 + t4*2;
            #pragma unroll
            for (int half = 0; half < 2; half++) {
                int rr = r + half*8;
                float v0 = c[mt][nt][half*2 + 0];
                float v1 = c[mt][nt][half*2 + 1];
                if (bias) { v0 += bias[cc]; v1 += bias[cc+1]; }
                if (GELU) {
                    v0 = 0.5f*v0*(1.0f + erff(v0*0.70710678118654752f));
                    v1 = 0.5f*v1*(1.0f + erff(v1*0.70710678118654752f));
                }
                if (HOUT) {
                    __half* Ch = (__half*)Cout;
                    *(__half2*)&Ch[(size_t)rr*K + cc] = __floats2half2_rn(v0, v1);
                } else {
                    float* Cf = (float*)Cout;
                    *(float2*)&Cf[(size_t)rr*K + cc] = make_float2(v0, v1);
                }
            }
        }
}

// ---------------- BD_raw via fp16 tensor cores ----------------
#define RS_WSTR 36
__global__ __launch_bounds__(256)
void bd_mma(const __half* __restrict__ q, int qrs, size_t qbs,
            const __half* __restrict__ r, int rrs,
            const float* __restrict__ vvec, float* __restrict__ bdout) {
    __shared__ uint32_t RsU[64*RS_WSTR];
    const int t0 = blockIdx.x * 64;
    const int i0 = blockIdx.y * 128;
    const int h = blockIdx.z & (HN-1), b = blockIdx.z >> 4;
    const int tid = threadIdx.x;
    const int lane = tid & 31, wid = tid >> 5;
    const int grp = lane >> 2, t4 = lane & 3;
    const int i_r0 = i0 + wid*16 + grp, i_r1 = i_r0 + 8;

    uint32_t qf[4][4];
    {
        const __half* qp0 = q + (size_t)b*qbs + (size_t)i_r0*qrs + h*DH;
        const __half* qp1 = q + (size_t)b*qbs + (size_t)i_r1*qrs + h*DH;
        const float* up  = vvec + h*DH;
        #pragma unroll
        for (int ks = 0; ks < 4; ks++) {
            int k0 = 16*ks + 2*t4;
            float ua = up[k0], ub = up[k0+1], uc = up[k0+8], ud = up[k0+9];
            qf[ks][0] = packh2(__half2float(qp0[k0])   + ua, __half2float(qp0[k0+1]) + ub);
            qf[ks][1] = packh2(__half2float(qp1[k0])   + ua, __half2float(qp1[k0+1]) + ub);
            qf[ks][2] = packh2(__half2float(qp0[k0+8]) + uc, __half2float(qp0[k0+9]) + ud);
            qf[ks][3] = packh2(__half2float(qp1[k0+8]) + uc, __half2float(qp1[k0+9]) + ud);
        }
    }
    #pragma unroll
    for (int t = 0; t < 2; t++) {
        int idx = tid + 256*t;
        int row = idx >> 3, c8 = (idx & 7) * 8;
        uint4 rv = *(const uint4*)&r[(size_t)(t0 + row)*rrs + h*DH + c8];
        *(uint4*)&RsU[row*RS_WSTR + (idx & 7)*4] = rv;
    }
    __syncthreads();

    float s[8][4];
    #pragma unroll
    for (int nt = 0; nt < 8; nt++)
        #pragma unroll
        for (int e = 0; e < 4; e++) s[nt][e] = 0.0f;

    #pragma unroll
    for (int ks = 0; ks < 4; ks++)
        #pragma unroll
        for (int nt = 0; nt < 8; nt++) {
            uint32_t b0 = RsU[(nt*8+grp)*RS_WSTR + t4 + 8*ks];
            uint32_t b1 = RsU[(nt*8+grp)*RS_WSTR + t4 + 4 + 8*ks];
            MMA_F16(s[nt], qf[ks][0], qf[ks][1], qf[ks][2], qf[ks][3], b0, b1);
        }

    float* o0 = bdout + (((size_t)(b*HN + h))*QN + i_r0)*KLEN + t0;
    float* o1 = bdout + (((size_t)(b*HN + h))*QN + i_r1)*KLEN + t0;
    #pragma unroll
    for (int nt = 0; nt < 8; nt++) {
        int cc = nt*8 + 2*t4;
        *(float2*)&o0[cc] = make_float2(s[nt][0], s[nt][1]);
        *(float2*)&o1[cc] = make_float2(s[nt][2], s[nt][3]);
    }
}

// ------- MMA flash attention: cp.async double-buffered K/V, all-fp16 -------
// smem words: Kst[2][64*36] | Vst[2][64*36] | Ps half[128][72] (=4608 words)
#define F_KST 0
#define F_VST 4608
#define F_PSH 9216
#define F_BUF 2304
#define PS_WSTR 36
#define FLASH_SMEM (13824*4)

__global__ __launch_bounds__(256, 2)
void flashmma(const __half* __restrict__ q, int qrs, size_t qbs,
              const __half* __restrict__ k, const __half* __restrict__ v,
              int kvrs, size_t kvbs,
              const float* __restrict__ bd, const float* __restrict__ uvec,
              __half* __restrict__ out, int klen, int useMask) {
    extern __shared__ uint32_t smu[];
    const uint32_t sb = smem_u32(smu);
    uint32_t* PsU = smu + F_PSH;

    const int i0 = blockIdx.x * 128;
    const int h = blockIdx.y, b = blockIdx.z;
    const int tid = threadIdx.x;
    const int lane = tid & 31, wid = tid >> 5;
    const int grp = lane >> 2, t4 = lane & 3;
    const int r0 = wid*16 + grp, r1 = r0 + 8;
    const int i_r0 = i0 + r0, i_r1 = i0 + r1;

    uint32_t qf[4][4];
    {
        const __half* qp0 = q + (size_t)b*qbs + (size_t)i_r0*qrs + h*DH;
        const __half* qp1 = q + (size_t)b*qbs + (size_t)i_r1*qrs + h*DH;
        #pragma unroll
        for (int ks = 0; ks < 4; ks++) {
            int k0 = 16*ks + 2*t4;
            float ua = uvec ? uvec[h*DH + k0]   : 0.0f;
            float ub = uvec ? uvec[h*DH + k0+1] : 0.0f;
            float uc = uvec ? uvec[h*DH + k0+8] : 0.0f;
            float ud = uvec ? uvec[h*DH + k0+9] : 0.0f;
            qf[ks][0] = packh2(__half2float(qp0[k0])   + ua, __half2float(qp0[k0+1]) + ub);
            qf[ks][1] = packh2(__half2float(qp1[k0])   + ua, __half2float(qp1[k0+1]) + ub);
            qf[ks][2] = packh2(__half2float(qp0[k0+8]) + uc, __half2float(qp0[k0+9]) + ud);
            qf[ks][3] = packh2(__half2float(qp1[k0+8]) + uc, __half2float(qp1[k0+9]) + ud);
        }
    }

    float m0 = -INFINITY, m1 = -INFINITY, l0 = 0.0f, l1 = 0.0f;
    float o[8][4];
    #pragma unroll
    for (int nt = 0; nt < 8; nt++)
        #pragma unroll
        for (int e = 0; e < 4; e++) o[nt][e] = 0.0f;

    const float* bdr0 = bd ? bd + (((size_t)(b*HN + h))*QN + i_r0)*KLEN : (const float*)0;
    const float* bdr1 = bd ? bd + (((size_t)(b*HN + h))*QN + i_r1)*KLEN : (const float*)0;

    int lastj = klen - 1;
    if (useMask) { int lm = i0 + 127 + MN; if (lm < lastj) lastj = lm; }
    const int nch = lastj/64 + 1;

    const int lrow0 = tid >> 3, lseg = tid & 7;
    const __half* kbase = k + (size_t)b*kvbs + h*DH + lseg*8;
    const __half* vbase = v + (size_t)b*kvbs + h*DH + lseg*8;
    const uint32_t vrowbase = sb + (F_VST + (lane & 15)*36)*4;

    // prologue: issue chunk 0
    {
        #pragma unroll
        for (int t = 0; t < 2; t++) {
            int row = lrow0 + 32*t;
            cp16(sb + (F_KST + row*36 + lseg*4)*4, kbase + (size_t)row*kvrs);
            cp16(sb + (F_VST + row*36 + lseg*4)*4, vbase + (size_t)row*kvrs);
        }
        CP_COMMIT();
    }

    for (int c = 0; c < nch; c++) {
        const int j0 = c*64;
        // prefetch chunk c+1
        if (c + 1 < nch) {
            const int bn = (c+1) & 1;
            const int jn = (c+1)*64;
            #pragma unroll
            for (int t = 0; t < 2; t++) {
                int row = lrow0 + 32*t;
                cp16(sb + (F_KST + bn*F_BUF + row*36 + lseg*4)*4,
                     kbase + (size_t)(jn + row)*kvrs);
                cp16(sb + (F_VST + bn*F_BUF + row*36 + lseg*4)*4,
                     vbase + (size_t)(jn + row)*kvrs);
            }
        }
        CP_COMMIT();
        asm volatile("cp.async.wait_group 1;\n" ::);
        __syncthreads();

        const uint32_t* KsU = smu + F_KST + (c & 1)*F_BUF;

        float bdv[8][4];
        if (bd) {
            #pragma unroll
            for (int nt = 0; nt < 8; nt++) {
                int jA = j0 + nt*8 + 2*t4;
                int jr0 = jA - i_r0 + (QN-1);
                int jr1 = jA - i_r1 + (QN-1);
                jr0 = max(0, min(KLEN-2, jr0));
                jr1 = max(0, min(KLEN-2, jr1));
                bdv[nt][0] = bdr0[jr0];   bdv[nt][1] = bdr0[jr0+1];
                bdv[nt][2] = bdr1[jr1];   bdv[nt][3] = bdr1[jr1+1];
            }
        }

        // S = Q @ K^T  (fp16)
        float s[8][4];
        #pragma unroll
        for (int nt = 0; nt < 8; nt++)
            #pragma unroll
            for (int e = 0; e < 4; e++) s[nt][e] = 0.0f;
        #pragma unroll
        for (int ks = 0; ks < 4; ks++)
            #pragma unroll
            for (int nt = 0; nt < 8; nt++) {
                uint32_t b0 = KsU[(nt*8+grp)*36 + t4 + 8*ks];
                uint32_t b1 = KsU[(nt*8+grp)*36 + t4 + 4 + 8*ks];
                MMA_F16(s[nt], qf[ks][0], qf[ks][1], qf[ks][2], qf[ks][3], b0, b1);
            }

        float mc0 = -INFINITY, mc1 = -INFINITY;
        #pragma unroll
        for (int nt = 0; nt < 8; nt++) {
            int jA = j0 + nt*8 + 2*t4;
            int jB = jA + 1;
            float v0 = s[nt][0], v1 = s[nt][1], v2 = s[nt][2], v3 = s[nt][3];
            if (bd) { v0 += bdv[nt][0]; v1 += bdv[nt][1]; v2 += bdv[nt][2]; v3 += bdv[nt][3]; }
            v0 *= 0.125f; v1 *= 0.125f; v2 *= 0.125f; v3 *= 0.125f;
            if (useMask) {
                if (jA > i_r0 + MN) v0 = -INFINITY;
                if (jB > i_r0 + MN) v1 = -INFINITY;
                if (jA > i_r1 + MN) v2 = -INFINITY;
                if (jB > i_r1 + MN) v3 = -INFINITY;
            }
            s[nt][0]=v0; s[nt][1]=v1; s[nt][2]=v2; s[nt][3]=v3;
            mc0 = fmaxf(mc0, fmaxf(v0, v1));
            mc1 = fmaxf(mc1, fmaxf(v2, v3));
        }
        mc0 = fmaxf(mc0, __shfl_xor_sync(0xffffffffu, mc0, 1));
        mc0 = fmaxf(mc0, __shfl_xor_sync(0xffffffffu, mc0, 2));
        mc1 = fmaxf(mc1, __shfl_xor_sync(0xffffffffu, mc1, 1));
        mc1 = fmaxf(mc1, __shfl_xor_sync(0xffffffffu, mc1, 2));

        float nm0 = fmaxf(m0, mc0), nm1 = fmaxf(m1, mc1);
        float corr0 = __expf(m0 - nm0), corr1 = __expf(m1 - nm1);
        float ps0 = 0.0f, ps1 = 0.0f;
        #pragma unroll
        for (int nt = 0; nt < 8; nt++) {
            float p0 = __expf(s[nt][0] - nm0);
            float p1 = __expf(s[nt][1] - nm0);
            float p2 = __expf(s[nt][2] - nm1);
            float p3 = __expf(s[nt][3] - nm1);
            ps0 += p0 + p1; ps1 += p2 + p3;
            PsU[r0*PS_WSTR + nt*4 + t4] = packh2(p0, p1);
            PsU[r1*PS_WSTR + nt*4 + t4] = packh2(p2, p3);
        }
        ps0 += __shfl_xor_sync(0xffffffffu, ps0, 1);
        ps0 += __shfl_xor_sync(0xffffffffu, ps0, 2);
        ps1 += __shfl_xor_sync(0xffffffffu, ps1, 1);
        ps1 += __shfl_xor_sync(0xffffffffu, ps1, 2);
        l0 = l0 * corr0 + ps0;  m0 = nm0;
        l1 = l1 * corr1 + ps1;  m1 = nm1;
        #pragma unroll
        for (int nt = 0; nt < 8; nt++) {
            o[nt][0] *= corr0; o[nt][1] *= corr0;
            o[nt][2] *= corr1; o[nt][3] *= corr1;
        }
        __syncwarp();

        // O += P @ V (fp16): P A-frags from PsU, V B-frags via ldmatrix.trans
        const uint32_t vrb = vrowbase + ((c & 1) ? F_BUF*4 : 0);
        #pragma unroll
        for (int ks = 0; ks < 4; ks++) {
            uint32_t a0 = PsU[r0*PS_WSTR + 8*ks + t4];
            uint32_t a1 = PsU[r1*PS_WSTR + 8*ks + t4];
            uint32_t a2 = PsU[r0*PS_WSTR + 8*ks + t4 + 4];
            uint32_t a3 = PsU[r1*PS_WSTR + 8*ks + t4 + 4];
            #pragma unroll
            for (int nt = 0; nt < 8; nt++) {
                uint32_t vb0, vb1;
                uint32_t vaddr = vrb + (ks*576 + nt*4)*4;
                asm volatile(
                    "ldmatrix.sync.aligned.m8n8.x2.trans.shared.b16 {%0,%1}, [%2];"
                    : "=r"(vb0), "=r"(vb1) : "r"(vaddr));
                MMA_F16(o[nt], a0, a1, a2, a3, vb0, vb1);
            }
        }
        __syncthreads();   // protect staging + Ps before next iteration
    }

    const float inv0 = 1.0f / l0, inv1 = 1.0f / l1;
    __half* op0 = out + ((size_t)(b*QN + i_r0))*DM + h*DH;
    __half* op1 = out + ((size_t)(b*QN + i_r1))*DM + h*DH;
    #pragma unroll
    for (int nt = 0; nt < 8; nt++) {
        int cc = nt*8 + 2*t4;
        *(__half2*)&op0[cc] = __floats2half2_rn(o[nt][0]*inv0, o[nt][1]*inv0);
        *(__half2*)&op1[cc] = __floats2half2_rn(o[nt][2]*inv1, o[nt][3]*inv1);
    }
}

// ------- residual add + LayerNorm (single-pass shuffle reduction) ----------
__global__ __launch_bounds__(256)
void ln_kernel(float* __restrict__ x, __half* __restrict__ xh,
               const float* __restrict__ y,
               const float* __restrict__ gamma, const float* __restrict__ beta) {
    const int row = blockIdx.x;
    const int tid = threadIdx.x;
    const int lane = tid & 31, wid = tid >> 5;
    __shared__ float rs[8], rq[8];

    float s[4];
    float sum = 0.0f, sq = 0.0f;
    #pragma unroll
    for (int kk = 0; kk < 4; kk++) {
        int c = tid + kk*256;
        float val = x[(size_t)row*DM + c] + y[(size_t)row*DM + c];
        s[kk] = val;
        sum += val;
        sq  = fmaf(val, val, sq);
    }
    #pragma unroll
    for (int d = 16; d > 0; d >>= 1) {
        sum += __shfl_xor_sync(0xffffffffu, sum, d);
        sq  += __shfl_xor_sync(0xffffffffu, sq,  d);
    }
    if (lane == 0) { rs[wid] = sum; rq[wid] = sq; }
    __syncthreads();
    float tot = 0.0f, totq = 0.0f;
    #pragma unroll
    for (int w = 0; w < 8; w++) { tot += rs[w]; totq += rq[w]; }
    const float mu = tot * (1.0f / DM);
    const float var = totq * (1.0f / DM) - mu * mu;
    const float rstd = rsqrtf(var + 1e-5f);

    #pragma unroll
    for (int kk = 0; kk < 4; kk++) {
        int c = tid + kk*256;
        float val = (s[kk] - mu) * rstd * gamma[c] + beta[c];
        x [(size_t)row*DM + c] = val;
        xh[(size_t)row*DM + c] = __float2half_rn(val);
    }
}

// ---------------- host orchestration ----------------
static inline void run_gemm(const __half* A, const __half* Bt, const float* bias,
                            void* C, int N, int D, int K, bool gelu, bool hout) {
    dim3 grid(K/128, N/128);
    if (gelu)      mm_h<true , true ><<<grid, 256, MM_SMEM>>>(A, Bt, bias, C, N, D, K);
    else if (hout) mm_h<false, true ><<<grid, 256, MM_SMEM>>>(A, Bt, bias, C, N, D, K);
    else           mm_h<false, false><<<grid, 256, MM_SMEM>>>(A, Bt, bias, C, N, D, K);
}

extern "C" void kernel_launch(void* const* d_in, const int* in_sizes, int n_in,
                              void* d_out, int out_size) {
    const float* enc    = (const float*)d_in[0];
    const float* mems   = (const float*)d_in[1];
    const float* emb    = (const float*)d_in[2];
    const float* u      = (const float*)d_in[3];
    const float* vpar   = (const float*)d_in[4];
    const float* saWq   = (const float*)d_in[5];
    const float* saWk   = (const float*)d_in[6];
    const float* saWv   = (const float*)d_in[7];
    const float* saWr   = (const float*)d_in[8];
    const float* safcW  = (const float*)d_in[9];
    const float* safcB  = (const float*)d_in[10];
    const float* ln1g   = (const float*)d_in[11];
    const float* ln1b   = (const float*)d_in[12];
    const float* caWq   = (const float*)d_in[13];
    const float* caWk   = (const float*)d_in[14];
    const float* caWv   = (const float*)d_in[15];
    const float* cafcW  = (const float*)d_in[16];
    const float* cafcB  = (const float*)d_in[17];
    const float* ln2g   = (const float*)d_in[18];
    const float* ln2b   = (const float*)d_in[19];
    const float* ffW1   = (const float*)d_in[20];
    const float* ffb1   = (const float*)d_in[21];
    const float* ffW2   = (const float*)d_in[22];
    const float* ffb2   = (const float*)d_in[23];
    const float* ln3g   = (const float*)d_in[24];
    const float* ln3b   = (const float*)d_in[25];
    const float* outW   = (const float*)d_in[26];
    const int*   ids    = (const int*)  d_in[27];
    float* out = (float*)d_out;

    float *x, *tmp, *bdb;
    __half *hxh, *hmem, *hqkv, *hcakv, *hr4, *hatt, *hq, *hff, *hremb, *henc;
    __half *wqkvh, *wcakvh, *wr4h, *wsafch, *wcafch, *wcaqh, *wff1h, *wff2h, *wouth;
    cudaGetSymbolAddress((void**)&x,      g_x);
    cudaGetSymbolAddress((void**)&tmp,    g_tmp);
    cudaGetSymbolAddress((void**)&bdb,    g_bd);
    cudaGetSymbolAddress((void**)&hxh,    g_hxh);
    cudaGetSymbolAddress((void**)&hmem,   g_hmem);
    cudaGetSymbolAddress((void**)&hqkv,   g_hqkv);
    cudaGetSymbolAddress((void**)&hcakv,  g_hcakv);
    cudaGetSymbolAddress((void**)&hr4,    g_hr4);
    cudaGetSymbolAddress((void**)&hatt,   g_hatt);
    cudaGetSymbolAddress((void**)&hq,     g_hq);
    cudaGetSymbolAddress((void**)&hff,    g_hff);
    cudaGetSymbolAddress((void**)&hremb,  g_hremb);
    cudaGetSymbolAddress((void**)&henc,   g_henc);
    cudaGetSymbolAddress((void**)&wqkvh,  g_wqkv);
    cudaGetSymbolAddress((void**)&wcakvh, g_wcakv);
    cudaGetSymbolAddress((void**)&wr4h,   g_wr4);
    cudaGetSymbolAddress((void**)&wsafch, g_wsafc);
    cudaGetSymbolAddress((void**)&wcafch, g_wcafc);
    cudaGetSymbolAddress((void**)&wcaqh,  g_wcaq);
    cudaGetSymbolAddress((void**)&wff1h,  g_wff1);
    cudaGetSymbolAddress((void**)&wff2h,  g_wff2);
    cudaGetSymbolAddress((void**)&wouth,  g_wout);

    static int smem_set = 0;
    if (!smem_set) {
        cudaFuncSetAttribute(flashmma, cudaFuncAttributeMaxDynamicSharedMemorySize,
                             FLASH_SMEM);
        cudaFuncSetAttribute((mm_h<true , true >), cudaFuncAttributeMaxDynamicSharedMemorySize, MM_SMEM);
        cudaFuncSetAttribute((mm_h<false, true >), cudaFuncAttributeMaxDynamicSharedMemorySize, MM_SMEM);
        cudaFuncSetAttribute((mm_h<false, false>), cudaFuncAttributeMaxDynamicSharedMemorySize, MM_SMEM);
        smem_set = 1;
    }

    // batched DM x DM transposes (9 weight groups x 4 layers, one launch)
    {
        TB9 tb;
        tb.s[0]=saWq;  tb.d[0]=wqkvh;                   tb.dbs[0]=(size_t)3072*DM;
        tb.s[1]=saWk;  tb.d[1]=wqkvh + (size_t)1024*DM; tb.dbs[1]=(size_t)3072*DM;
        tb.s[2]=saWv;  tb.d[2]=wqkvh + (size_t)2048*DM; tb.dbs[2]=(size_t)3072*DM;
        tb.s[3]=caWk;  tb.d[3]=wcakvh;                  tb.dbs[3]=(size_t)2048*DM;
        tb.s[4]=caWv;  tb.d[4]=wcakvh + (size_t)1024*DM;tb.dbs[4]=(size_t)2048*DM;
        tb.s[5]=saWr;  tb.d[5]=wr4h;                    tb.dbs[5]=(size_t)DM*DM;
        tb.s[6]=safcW; tb.d[6]=wsafch;                  tb.dbs[6]=(size_t)DM*DM;
        tb.s[7]=cafcW; tb.d[7]=wcafch;                  tb.dbs[7]=(size_t)DM*DM;
        tb.s[8]=caWq;  tb.d[8]=wcaqh;                   tb.dbs[8]=(size_t)DM*DM;
        trans_half9<<<dim3(DM/32, DM/32, 36), dim3(32, 8)>>>(tb);
    }
    dim3 tb2(32, 8);
    trans_half<<<dim3(FFN/32, DM/32, LNUM), tb2>>>(ffW1, wff1h, DM, FFN, (size_t)DM*FFN, (size_t)DM*FFN);
    trans_half<<<dim3(DM/32, FFN/32, LNUM), tb2>>>(ffW2, wff2h, FFN, DM, (size_t)DM*FFN, (size_t)DM*FFN);
    trans_half<<<dim3(VN/32, DM/32, 1),     tb2>>>(outW, wouth, DM, VN, 0, 0);
    half_copy<<<((BN*EN*DM/4) + 255)/256, 256>>>(enc, henc, BN*EN*DM/4);

    embed_kernel<<<(BN*QN*DM + 255)/256, 256>>>(ids, emb, x);
    remb_kernel <<<(KLEN*DM + 255)/256, 256>>>(hremb);

    // layer-independent projections (fused across layers)
    run_gemm(hremb, wr4h,   nullptr, hr4,   KLEN,  DM, 4096, false, true);
    run_gemm(henc,  wcakvh, nullptr, hcakv, BN*EN, DM, 8192, false, true);

    dim3 flash_grid(QN/128, HN, BN);
    dim3 bd_grid(KLEN/64, QN/128, BN*HN);

    for (int l = 0; l < LNUM; l++) {
        // ---- self-attention (TransformerXL relative) ----
        concat_kernel<<<(BN*KLEN*DM + 255)/256, 256>>>(
            mems + (size_t)l*BN*MN*DM, x, hmem);

        run_gemm(hmem, wqkvh + (size_t)l*3072*DM, nullptr, hqkv,
                 BN*KLEN, DM, 3072, false, true);

        const __half* qself = hqkv + (size_t)MN*3072;
        bd_mma<<<bd_grid, 256>>>(qself, 3072, (size_t)KLEN*3072,
                                 hr4 + (size_t)l*1024, 4096, vpar, bdb);
        flashmma<<<flash_grid, 256, FLASH_SMEM>>>(
            qself, 3072, (size_t)KLEN*3072,
            hqkv + 1024, hqkv + 2048, 3072, (size_t)KLEN*3072,
            bdb, u, hatt, KLEN, 1);

        run_gemm(hatt, wsafch + (size_t)l*DM*DM, safcB + (size_t)l*DM,
                 tmp, BN*QN, DM, DM, false, false);
        ln_kernel<<<BN*QN, 256>>>(x, hxh, tmp, ln1g + (size_t)l*DM, ln1b + (size_t)l*DM);

        // ---- cross-attention ----
        run_gemm(hxh, wcaqh + (size_t)l*DM*DM, nullptr, hq, BN*QN, DM, DM, false, true);

        flashmma<<<flash_grid, 256, FLASH_SMEM>>>(
            hq, DM, (size_t)QN*DM,
            hcakv + (size_t)l*2048, hcakv + (size_t)l*2048 + 1024,
            8192, (size_t)EN*8192,
            nullptr, nullptr, hatt, EN, 0);

        run_gemm(hatt, wcafch + (size_t)l*DM*DM, cafcB + (size_t)l*DM,
                 tmp, BN*QN, DM, DM, false, false);
        ln_kernel<<<BN*QN, 256>>>(x, hxh, tmp, ln2g + (size_t)l*DM, ln2b + (size_t)l*DM);

        // ---- feed-forward ----
        run_gemm(hxh, wff1h + (size_t)l*DM*FFN, ffb1 + (size_t)l*FFN,
                 hff, BN*QN, DM, FFN, true, true);
        run_gemm(hff, wff2h + (size_t)l*DM*FFN, ffb2 + (size_t)l*DM,
                 tmp, BN*QN, FFN, DM, false, false);
        ln_kernel<<<BN*QN, 256>>>(x, hxh, tmp, ln3g + (size_t)l*DM, ln3b + (size_t)l*DM);
    }

    // ---- output projection ----
    run_gemm(hxh, wouth, nullptr, out, BN*QN, DM, VN, false, false);
}

// round 15
// speedup vs baseline: 1.2544x; 1.0545x over previous
#include <cuda_runtime.h>
#include <cuda_fp16.h>
#include <math.h>
#include <stdint.h>

// Problem constants
#define LNUM 4
#define DM   1024
#define HN   16
#define DH   64
#define FFN  4096
#define VN   8192
#define BN   4
#define QN   512
#define MN   512
#define EN   512
#define KLEN 1024   // M + Q

// ---------------- scratch (device globals; no allocation) ----------------
__device__ float  g_x   [BN*QN*DM];         // residual stream (full fp32)
__device__ float  g_tmp [BN*QN*DM];
__device__ float  g_bd  [BN*HN*QN*KLEN];
// half activation buffers
__device__ __half g_hxh  [BN*QN*DM];
__device__ __half g_hmem [BN*KLEN*DM];
__device__ __half g_hkv  [BN*KLEN*2048];
__device__ __half g_hcakv[BN*EN*8192];
__device__ __half g_hr4  [KLEN*4096];
__device__ __half g_hatt [BN*QN*DM];
__device__ __half g_hq   [BN*QN*DM];
__device__ __half g_hff  [BN*QN*FFN];
__device__ __half g_hremb[KLEN*DM];
__device__ __half g_henc [BN*EN*DM];
// transposed half weights (B^T, [n][k] row-major), built per call
__device__ __half g_wqkv [LNUM*3072*DM];
__device__ __half g_wcakv[8192*DM];
__device__ __half g_wr4  [4096*DM];
__device__ __half g_wsafc[LNUM*DM*DM];
__device__ __half g_wcafc[LNUM*DM*DM];
__device__ __half g_wcaq [LNUM*DM*DM];
__device__ __half g_wff1 [LNUM*FFN*DM];
__device__ __half g_wff2 [LNUM*DM*FFN];
__device__ __half g_wout [VN*DM];

// ---------------- helpers ----------------
#define MMA_F16(C, A0, A1, A2, A3, B0, B1)                                    \
    asm volatile(                                                             \
        "mma.sync.aligned.m16n8k16.row.col.f32.f16.f16.f32 "                  \
        "{%0,%1,%2,%3}, {%4,%5,%6,%7}, {%8,%9}, {%0,%1,%2,%3};"               \
        : "+f"((C)[0]), "+f"((C)[1]), "+f"((C)[2]), "+f"((C)[3])              \
        : "r"(A0), "r"(A1), "r"(A2), "r"(A3), "r"(B0), "r"(B1))

#define LDSM4(R0, R1, R2, R3, addr)                                           \
    asm volatile("ldmatrix.sync.aligned.m8n8.x4.shared.b16 {%0,%1,%2,%3}, [%4];" \
        : "=r"(R0), "=r"(R1), "=r"(R2), "=r"(R3) : "r"(addr))

__device__ __forceinline__ void cp16(uint32_t dst, const void* src) {
    asm volatile("cp.async.cg.shared.global [%0], [%1], 16;\n" :: "r"(dst), "l"(src));
}
#define CP_COMMIT()  asm volatile("cp.async.commit_group;\n" ::)

__device__ __forceinline__ uint32_t smem_u32(const void* p) {
    uint32_t a;
    asm("{ .reg .u64 t; cvta.to.shared.u64 t, %1; cvt.u32.u64 %0, t; }"
        : "=r"(a) : "l"(p));
    return a;
}
__device__ __forceinline__ uint32_t packh2(float a, float b) {
    __half2 h = __floats2half2_rn(a, b);
    return *(uint32_t*)&h;
}

// ---------------- elementwise kernels ----------------
__global__ void half_copy(const float* __restrict__ src,
                          __half* __restrict__ dst, int n4) {
    int i = blockIdx.x * blockDim.x + threadIdx.x;
    if (i >= n4) return;
    float4 v = ((const float4*)src)[i];
    ((__half2*)dst)[2*i]   = __floats2half2_rn(v.x, v.y);
    ((__half2*)dst)[2*i+1] = __floats2half2_rn(v.z, v.w);
}

// transpose + half: src [R, C] fp32 row-major -> dst [C, R] half row-major
__global__ void trans_half(const float* __restrict__ src, __half* __restrict__ dst,
                           int R, int C, size_t sbs, size_t dbs) {
    __shared__ float t[32][33];
    const float* s = src + (size_t)blockIdx.z * sbs;
    __half*      d = dst + (size_t)blockIdx.z * dbs;
    int c0 = blockIdx.x * 32, r0 = blockIdx.y * 32;
    int tx = threadIdx.x, ty = threadIdx.y;
    #pragma unroll
    for (int i = 0; i < 4; i++)
        t[ty + 8*i][tx] = s[(size_t)(r0 + ty + 8*i) * C + c0 + tx];
    __syncthreads();
    #pragma unroll
    for (int i = 0; i < 4; i++)
        d[(size_t)(c0 + ty + 8*i) * R + r0 + tx] = __float2half_rn(t[tx][ty + 8*i]);
}

// batched DM x DM transpose+convert: 9 weight groups x LNUM layers, one launch
struct TB9 {
    const float* s[9];
    __half*      d[9];
    unsigned long long dbs[9];
};
__global__ void trans_half9(TB9 tb) {
    __shared__ float t[32][33];
    const int idx = blockIdx.z >> 2;
    const int l   = blockIdx.z & 3;
    const float* s = tb.s[idx] + (size_t)l * DM * DM;
    __half*      d = tb.d[idx] + (size_t)l * tb.dbs[idx];
    int c0 = blockIdx.x * 32, r0 = blockIdx.y * 32;
    int tx = threadIdx.x, ty = threadIdx.y;
    #pragma unroll
    for (int i = 0; i < 4; i++)
        t[ty + 8*i][tx] = s[(size_t)(r0 + ty + 8*i) * DM + c0 + tx];
    __syncthreads();
    #pragma unroll
    for (int i = 0; i < 4; i++)
        d[(size_t)(c0 + ty + 8*i) * DM + r0 + tx] = __float2half_rn(t[tx][ty + 8*i]);
}

__global__ void embed_kernel(const int* __restrict__ ids,
                             const float* __restrict__ emb,
                             float* __restrict__ x, __half* __restrict__ xh) {
    int idx = blockIdx.x * blockDim.x + threadIdx.x;
    if (idx >= BN*QN*DM) return;
    int row = idx / DM;
    int d   = idx - row * DM;
    int tok = ids[row];
    float v = emb[tok * DM + d] * 32.0f;
    x[idx]  = v;
    xh[idx] = __float2half_rn(v);
}

__global__ void remb_kernel(__half* __restrict__ remb) {
    int idx = blockIdx.x * blockDim.x + threadIdx.x;
    if (idx >= KLEN*DM) return;
    int p = idx / DM;
    int d = idx - p * DM;
    float pos = (float)(KLEN - 1 - p);
    int k = (d < DM/2) ? d : d - DM/2;
    float invf = powf(10000.0f, -(float)k / (float)(DM/2));
    float a = pos * invf;
    remb[idx] = __float2half_rn((d < DM/2) ? sinf(a) : cosf(a));
}

__global__ void concat_kernel(const float* __restrict__ mems_l,
                              const float* __restrict__ x,
                              __half* __restrict__ mem) {
    int idx = blockIdx.x * blockDim.x + threadIdx.x;
    if (idx >= BN*KLEN*DM) return;
    int d   = idx % DM;
    int rem = idx / DM;
    int j   = rem % KLEN;
    int b   = rem / KLEN;
    float val;
    if (j < MN) val = mems_l[(b*MN + j)*DM + d];
    else        val = x[(b*QN + (j - MN))*DM + d];
    mem[idx] = __float2half_rn(val);
}

// ---------------- fp16 tensor-core GEMM, 4-stage cp.async, 2 CTAs/SM -------
// Fragments via ldmatrix.x4 (mapping verified against the scalar-LDS path).
#define STG    4
#define ROWU   12
#define TILE_U (128*ROWU)
#define STAGE_U (2*TILE_U)
#define MM_SMEM (STG*STAGE_U*4)

template<bool GELU, bool HOUT>
__global__ __launch_bounds__(256, 2)
void mm_h(const __half* __restrict__ A, const __half* __restrict__ Bt,
          const float* __restrict__ bias, void* __restrict__ Cout,
          int N, int D, int K) {
    extern __shared__ uint32_t smu[];
    const uint32_t sb = smem_u32(smu);

    const int tid  = threadIdx.x;
    const int row0 = blockIdx.y * 128, col0 = blockIdx.x * 128;
    const int lane = tid & 31, wid = tid >> 5;
    const int grp  = lane >> 2, t4 = lane & 3;
    const int wm   = (wid & 3) * 32, wn = (wid >> 2) * 64;

    const int lrow = tid >> 1;
    const int lseg = tid & 1;
    const __half* Ag = A  + (size_t)(row0 + lrow) * D + lseg * 8;
    const __half* Bg = Bt + (size_t)(col0 + lrow) * D + lseg * 8;
    const uint32_t dstA = sb + (lrow*ROWU + lseg*4) * 4;
    const uint32_t dstB = dstA + TILE_U*4;

    // ldmatrix lane address offsets (bytes)
    const uint32_t aoffB = (uint32_t)(((wm + (lane & 15))*ROWU + (lane >> 4)*4) * 4);
    const int bnt = lane >> 4, bkc = (lane >> 3) & 1, brw = lane & 7;
    uint32_t boffB[4];
    #pragma unroll
    for (int p = 0; p < 4; p++)
        boffB[p] = (uint32_t)((TILE_U + (wn + (2*p + bnt)*8 + brw)*ROWU + bkc*4) * 4);

    const int KT = D >> 4;

    float c[2][8][4];
    #pragma unroll
    for (int i = 0; i < 2; i++)
        #pragma unroll
        for (int j = 0; j < 8; j++)
            #pragma unroll
            for (int t = 0; t < 4; t++) c[i][j][t] = 0.0f;

    #pragma unroll
    for (int s = 0; s < STG-1; s++) {
        cp16(dstA + s*STAGE_U*4, Ag + (size_t)s*16);
        cp16(dstB + s*STAGE_U*4, Bg + (size_t)s*16);
        CP_COMMIT();
    }

    for (int kt = 0; kt < KT; kt++) {
        asm volatile("cp.async.wait_group 2;\n" ::);
        __syncthreads();
        const int st = kt & (STG-1);
        const uint32_t stb = sb + st*STAGE_U*4;

        uint32_t af[2][4], bf[8][2];
        LDSM4(af[0][0], af[0][1], af[0][2], af[0][3], stb + aoffB);
        LDSM4(af[1][0], af[1][1], af[1][2], af[1][3], stb + aoffB + 16*ROWU*4);
        LDSM4(bf[0][0], bf[0][1], bf[1][0], bf[1][1], stb + boffB[0]);
        LDSM4(bf[2][0], bf[2][1], bf[3][0], bf[3][1], stb + boffB[1]);
        LDSM4(bf[4][0], bf[4][1], bf[5][0], bf[5][1], stb + boffB[2]);
        LDSM4(bf[6][0], bf[6][1], bf[7][0], bf[7][1], stb + boffB[3]);

        const int kn = kt + STG - 1;
        if (kn < KT) {
            const int sn = kn & (STG-1);
            cp16(dstA + sn*STAGE_U*4, Ag + (size_t)kn*16);
            cp16(dstB + sn*STAGE_U*4, Bg + (size_t)kn*16);
        }
        CP_COMMIT();

        #pragma unroll
        for (int mt = 0; mt < 2; mt++)
            #pragma unroll
            for (int nt = 0; nt < 8; nt++)
                MMA_F16(c[mt][nt], af[mt][0], af[mt][1], af[mt][2], af[mt][3],
                        bf[nt][0], bf[nt][1]);
    }

    #pragma unroll
    for (int mt = 0; mt < 2; mt++)
        #pragma unroll
        for (int nt = 0; nt < 8; nt++) {
            int r  = row0 + wm + mt*16 + grp;
            int cc = col0 + wn + nt*8 + t4*2;
            #pragma unroll
            for (int half = 0; half < 2; half++) {
                int rr = r + half*8;
                float v0 = c[mt][nt][half*2 + 0];
                float v1 = c[mt][nt][half*2 + 1];
                if (bias) { v0 += bias[cc]; v1 += bias[cc+1]; }
                if (GELU) {
                    v0 = 0.5f*v0*(1.0f + erff(v0*0.70710678118654752f));
                    v1 = 0.5f*v1*(1.0f + erff(v1*0.70710678118654752f));
                }
                if (HOUT) {
                    __half* Ch = (__half*)Cout;
                    *(__half2*)&Ch[(size_t)rr*K + cc] = __floats2half2_rn(v0, v1);
                } else {
                    float* Cf = (float*)Cout;
                    *(float2*)&Cf[(size_t)rr*K + cc] = make_float2(v0, v1);
                }
            }
        }
}

// ---------------- BD_raw via fp16 tensor cores ----------------
#define RS_WSTR 36
__global__ __launch_bounds__(256)
void bd_mma(const __half* __restrict__ q, int qrs, size_t qbs,
            const __half* __restrict__ r, int rrs,
            const float* __restrict__ vvec, float* __restrict__ bdout) {
    __shared__ uint32_t RsU[64*RS_WSTR];
    const int t0 = blockIdx.x * 64;
    const int i0 = blockIdx.y * 128;
    const int h = blockIdx.z & (HN-1), b = blockIdx.z >> 4;
    const int tid = threadIdx.x;
    const int lane = tid & 31, wid = tid >> 5;
    const int grp = lane >> 2, t4 = lane & 3;
    const int i_r0 = i0 + wid*16 + grp, i_r1 = i_r0 + 8;

    uint32_t qf[4][4];
    {
        const __half* qp0 = q + (size_t)b*qbs + (size_t)i_r0*qrs + h*DH;
        const __half* qp1 = q + (size_t)b*qbs + (size_t)i_r1*qrs + h*DH;
        const float* up  = vvec + h*DH;
        #pragma unroll
        for (int ks = 0; ks < 4; ks++) {
            int k0 = 16*ks + 2*t4;
            float ua = up[k0], ub = up[k0+1], uc = up[k0+8], ud = up[k0+9];
            qf[ks][0] = packh2(__half2float(qp0[k0])   + ua, __half2float(qp0[k0+1]) + ub);
            qf[ks][1] = packh2(__half2float(qp1[k0])   + ua, __half2float(qp1[k0+1]) + ub);
            qf[ks][2] = packh2(__half2float(qp0[k0+8]) + uc, __half2float(qp0[k0+9]) + ud);
            qf[ks][3] = packh2(__half2float(qp1[k0+8]) + uc, __half2float(qp1[k0+9]) + ud);
        }
    }
    #pragma unroll
    for (int t = 0; t < 2; t++) {
        int idx = tid + 256*t;
        int row = idx >> 3, c8 = (idx & 7) * 8;
        uint4 rv = *(const uint4*)&r[(size_t)(t0 + row)*rrs + h*DH + c8];
        *(uint4*)&RsU[row*RS_WSTR + (idx & 7)*4] = rv;
    }
    __syncthreads();

    float s[8][4];
    #pragma unroll
    for (int nt = 0; nt < 8; nt++)
        #pragma unroll
        for (int e = 0; e < 4; e++) s[nt][e] = 0.0f;

    #pragma unroll
    for (int ks = 0; ks < 4; ks++)
        #pragma unroll
        for (int nt = 0; nt < 8; nt++) {
            uint32_t b0 = RsU[(nt*8+grp)*RS_WSTR + t4 + 8*ks];
            uint32_t b1 = RsU[(nt*8+grp)*RS_WSTR + t4 + 4 + 8*ks];
            MMA_F16(s[nt], qf[ks][0], qf[ks][1], qf[ks][2], qf[ks][3], b0, b1);
        }

    float* o0 = bdout + (((size_t)(b*HN + h))*QN + i_r0)*KLEN + t0;
    float* o1 = bdout + (((size_t)(b*HN + h))*QN + i_r1)*KLEN + t0;
    #pragma unroll
    for (int nt = 0; nt < 8; nt++) {
        int cc = nt*8 + 2*t4;
        *(float2*)&o0[cc] = make_float2(s[nt][0], s[nt][1]);
        *(float2*)&o1[cc] = make_float2(s[nt][2], s[nt][3]);
    }
}

// ------- MMA flash attention: cp.async double-buffered K/V, all-fp16 -------
#define F_KST 0
#define F_VST 4608
#define F_PSH 9216
#define F_BUF 2304
#define PS_WSTR 36
#define FLASH_SMEM (13824*4)

__global__ __launch_bounds__(256, 2)
void flashmma(const __half* __restrict__ q, int qrs, size_t qbs,
              const __half* __restrict__ k, const __half* __restrict__ v,
              int kvrs, size_t kvbs,
              const float* __restrict__ bd, const float* __restrict__ uvec,
              __half* __restrict__ out, int klen, int useMask) {
    extern __shared__ uint32_t smu[];
    const uint32_t sb = smem_u32(smu);
    uint32_t* PsU = smu + F_PSH;

    const int i0 = blockIdx.x * 128;
    const int h = blockIdx.y, b = blockIdx.z;
    const int tid = threadIdx.x;
    const int lane = tid & 31, wid = tid >> 5;
    const int grp = lane >> 2, t4 = lane & 3;
    const int r0 = wid*16 + grp, r1 = r0 + 8;
    const int i_r0 = i0 + r0, i_r1 = i0 + r1;

    uint32_t qf[4][4];
    {
        const __half* qp0 = q + (size_t)b*qbs + (size_t)i_r0*qrs + h*DH;
        const __half* qp1 = q + (size_t)b*qbs + (size_t)i_r1*qrs + h*DH;
        #pragma unroll
        for (int ks = 0; ks < 4; ks++) {
            int k0 = 16*ks + 2*t4;
            float ua = uvec ? uvec[h*DH + k0]   : 0.0f;
            float ub = uvec ? uvec[h*DH + k0+1] : 0.0f;
            float uc = uvec ? uvec[h*DH + k0+8] : 0.0f;
            float ud = uvec ? uvec[h*DH + k0+9] : 0.0f;
            qf[ks][0] = packh2(__half2float(qp0[k0])   + ua, __half2float(qp0[k0+1]) + ub);
            qf[ks][1] = packh2(__half2float(qp1[k0])   + ua, __half2float(qp1[k0+1]) + ub);
            qf[ks][2] = packh2(__half2float(qp0[k0+8]) + uc, __half2float(qp0[k0+9]) + ud);
            qf[ks][3] = packh2(__half2float(qp1[k0+8]) + uc, __half2float(qp1[k0+9]) + ud);
        }
    }

    float m0 = -INFINITY, m1 = -INFINITY, l0 = 0.0f, l1 = 0.0f;
    float o[8][4];
    #pragma unroll
    for (int nt = 0; nt < 8; nt++)
        #pragma unroll
        for (int e = 0; e < 4; e++) o[nt][e] = 0.0f;

    const float* bdr0 = bd ? bd + (((size_t)(b*HN + h))*QN + i_r0)*KLEN : (const float*)0;
    const float* bdr1 = bd ? bd + (((size_t)(b*HN + h))*QN + i_r1)*KLEN : (const float*)0;

    int lastj = klen - 1;
    if (useMask) { int lm = i0 + 127 + MN; if (lm < lastj) lastj = lm; }
    const int nch = lastj/64 + 1;

    const int lrow0 = tid >> 3, lseg = tid & 7;
    const __half* kbase = k + (size_t)b*kvbs + h*DH + lseg*8;
    const __half* vbase = v + (size_t)b*kvbs + h*DH + lseg*8;
    const uint32_t vrowbase = sb + (F_VST + (lane & 15)*36)*4;

    {
        #pragma unroll
        for (int t = 0; t < 2; t++) {
            int row = lrow0 + 32*t;
            cp16(sb + (F_KST + row*36 + lseg*4)*4, kbase + (size_t)row*kvrs);
            cp16(sb + (F_VST + row*36 + lseg*4)*4, vbase + (size_t)row*kvrs);
        }
        CP_COMMIT();
    }

    for (int c = 0; c < nch; c++) {
        const int j0 = c*64;
        if (c + 1 < nch) {
            const int bn = (c+1) & 1;
            const int jn = (c+1)*64;
            #pragma unroll
            for (int t = 0; t < 2; t++) {
                int row = lrow0 + 32*t;
                cp16(sb + (F_KST + bn*F_BUF + row*36 + lseg*4)*4,
                     kbase + (size_t)(jn + row)*kvrs);
                cp16(sb + (F_VST + bn*F_BUF + row*36 + lseg*4)*4,
                     vbase + (size_t)(jn + row)*kvrs);
            }
        }
        CP_COMMIT();
        asm volatile("cp.async.wait_group 1;\n" ::);
        __syncthreads();

        const uint32_t* KsU = smu + F_KST + (c & 1)*F_BUF;

        float bdv[8][4];
        if (bd) {
            #pragma unroll
            for (int nt = 0; nt < 8; nt++) {
                int jA = j0 + nt*8 + 2*t4;
                int jr0 = jA - i_r0 + (QN-1);
                int jr1 = jA - i_r1 + (QN-1);
                jr0 = max(0, min(KLEN-2, jr0));
                jr1 = max(0, min(KLEN-2, jr1));
                bdv[nt][0] = bdr0[jr0];   bdv[nt][1] = bdr0[jr0+1];
                bdv[nt][2] = bdr1[jr1];   bdv[nt][3] = bdr1[jr1+1];
            }
        }

        float s[8][4];
        #pragma unroll
        for (int nt = 0; nt < 8; nt++)
            #pragma unroll
            for (int e = 0; e < 4; e++) s[nt][e] = 0.0f;
        #pragma unroll
        for (int ks = 0; ks < 4; ks++)
            #pragma unroll
            for (int nt = 0; nt < 8; nt++) {
                uint32_t b0 = KsU[(nt*8+grp)*36 + t4 + 8*ks];
                uint32_t b1 = KsU[(nt*8+grp)*36 + t4 + 4 + 8*ks];
                MMA_F16(s[nt], qf[ks][0], qf[ks][1], qf[ks][2], qf[ks][3], b0, b1);
            }

        float mc0 = -INFINITY, mc1 = -INFINITY;
        #pragma unroll
        for (int nt = 0; nt < 8; nt++) {
            int jA = j0 + nt*8 + 2*t4;
            int jB = jA + 1;
            float v0 = s[nt][0], v1 = s[nt][1], v2 = s[nt][2], v3 = s[nt][3];
            if (bd) { v0 += bdv[nt][0]; v1 += bdv[nt][1]; v2 += bdv[nt][2]; v3 += bdv[nt][3]; }
            v0 *= 0.125f; v1 *= 0.125f; v2 *= 0.125f; v3 *= 0.125f;
            if (useMask) {
                if (jA > i_r0 + MN) v0 = -INFINITY;
                if (jB > i_r0 + MN) v1 = -INFINITY;
                if (jA > i_r1 + MN) v2 = -INFINITY;
                if (jB > i_r1 + MN) v3 = -INFINITY;
            }
            s[nt][0]=v0; s[nt][1]=v1; s[nt][2]=v2; s[nt][3]=v3;
            mc0 = fmaxf(mc0, fmaxf(v0, v1));
            mc1 = fmaxf(mc1, fmaxf(v2, v3));
        }
        mc0 = fmaxf(mc0, __shfl_xor_sync(0xffffffffu, mc0, 1));
        mc0 = fmaxf(mc0, __shfl_xor_sync(0xffffffffu, mc0, 2));
        mc1 = fmaxf(mc1, __shfl_xor_sync(0xffffffffu, mc1, 1));
        mc1 = fmaxf(mc1, __shfl_xor_sync(0xffffffffu, mc1, 2));

        float nm0 = fmaxf(m0, mc0), nm1 = fmaxf(m1, mc1);
        float corr0 = __expf(m0 - nm0), corr1 = __expf(m1 - nm1);
        float ps0 = 0.0f, ps1 = 0.0f;
        #pragma unroll
        for (int nt = 0; nt < 8; nt++) {
            float p0 = __expf(s[nt][0] - nm0);
            float p1 = __expf(s[nt][1] - nm0);
            float p2 = __expf(s[nt][2] - nm1);
            float p3 = __expf(s[nt][3] - nm1);
            ps0 += p0 + p1; ps1 += p2 + p3;
            PsU[r0*PS_WSTR + nt*4 + t4] = packh2(p0, p1);
            PsU[r1*PS_WSTR + nt*4 + t4] = packh2(p2, p3);
        }
        ps0 += __shfl_xor_sync(0xffffffffu, ps0, 1);
        ps0 += __shfl_xor_sync(0xffffffffu, ps0, 2);
        ps1 += __shfl_xor_sync(0xffffffffu, ps1, 1);
        ps1 += __shfl_xor_sync(0xffffffffu, ps1, 2);
        l0 = l0 * corr0 + ps0;  m0 = nm0;
        l1 = l1 * corr1 + ps1;  m1 = nm1;
        #pragma unroll
        for (int nt = 0; nt < 8; nt++) {
            o[nt][0] *= corr0; o[nt][1] *= corr0;
            o[nt][2] *= corr1; o[nt][3] *= corr1;
        }
        __syncwarp();

        const uint32_t vrb = vrowbase + ((c & 1) ? F_BUF*4 : 0);
        #pragma unroll
        for (int ks = 0; ks < 4; ks++) {
            uint32_t a0 = PsU[r0*PS_WSTR + 8*ks + t4];
            uint32_t a1 = PsU[r1*PS_WSTR + 8*ks + t4];
            uint32_t a2 = PsU[r0*PS_WSTR + 8*ks + t4 + 4];
            uint32_t a3 = PsU[r1*PS_WSTR + 8*ks + t4 + 4];
            #pragma unroll
            for (int nt = 0; nt < 8; nt++) {
                uint32_t vb0, vb1;
                uint32_t vaddr = vrb + (ks*576 + nt*4)*4;
                asm volatile(
                    "ldmatrix.sync.aligned.m8n8.x2.trans.shared.b16 {%0,%1}, [%2];"
                    : "=r"(vb0), "=r"(vb1) : "r"(vaddr));
                MMA_F16(o[nt], a0, a1, a2, a3, vb0, vb1);
            }
        }
        __syncthreads();
    }

    const float inv0 = 1.0f / l0, inv1 = 1.0f / l1;
    __half* op0 = out + ((size_t)(b*QN + i_r0))*DM + h*DH;
    __half* op1 = out + ((size_t)(b*QN + i_r1))*DM + h*DH;
    #pragma unroll
    for (int nt = 0; nt < 8; nt++) {
        int cc = nt*8 + 2*t4;
        *(__half2*)&op0[cc] = __floats2half2_rn(o[nt][0]*inv0, o[nt][1]*inv0);
        *(__half2*)&op1[cc] = __floats2half2_rn(o[nt][2]*inv1, o[nt][3]*inv1);
    }
}

// ------- residual add + LayerNorm (single-pass shuffle reduction) ----------
__global__ __launch_bounds__(256)
void ln_kernel(float* __restrict__ x, __half* __restrict__ xh,
               const float* __restrict__ y,
               const float* __restrict__ gamma, const float* __restrict__ beta) {
    const int row = blockIdx.x;
    const int tid = threadIdx.x;
    const int lane = tid & 31, wid = tid >> 5;
    __shared__ float rs[8], rq[8];

    float s[4];
    float sum = 0.0f, sq = 0.0f;
    #pragma unroll
    for (int kk = 0; kk < 4; kk++) {
        int c = tid + kk*256;
        float val = x[(size_t)row*DM + c] + y[(size_t)row*DM + c];
        s[kk] = val;
        sum += val;
        sq  = fmaf(val, val, sq);
    }
    #pragma unroll
    for (int d = 16; d > 0; d >>= 1) {
        sum += __shfl_xor_sync(0xffffffffu, sum, d);
        sq  += __shfl_xor_sync(0xffffffffu, sq,  d);
    }
    if (lane == 0) { rs[wid] = sum; rq[wid] = sq; }
    __syncthreads();
    float tot = 0.0f, totq = 0.0f;
    #pragma unroll
    for (int w = 0; w < 8; w++) { tot += rs[w]; totq += rq[w]; }
    const float mu = tot * (1.0f / DM);
    const float var = totq * (1.0f / DM) - mu * mu;
    const float rstd = rsqrtf(var + 1e-5f);

    #pragma unroll
    for (int kk = 0; kk < 4; kk++) {
        int c = tid + kk*256;
        float val = (s[kk] - mu) * rstd * gamma[c] + beta[c];
        x [(size_t)row*DM + c] = val;
        xh[(size_t)row*DM + c] = __float2half_rn(val);
    }
}

// ---------------- host orchestration ----------------
static inline void run_gemm(const __half* A, const __half* Bt, const float* bias,
                            void* C, int N, int D, int K, bool gelu, bool hout) {
    dim3 grid(K/128, N/128);
    if (gelu)      mm_h<true , true ><<<grid, 256, MM_SMEM>>>(A, Bt, bias, C, N, D, K);
    else if (hout) mm_h<false, true ><<<grid, 256, MM_SMEM>>>(A, Bt, bias, C, N, D, K);
    else           mm_h<false, false><<<grid, 256, MM_SMEM>>>(A, Bt, bias, C, N, D, K);
}

extern "C" void kernel_launch(void* const* d_in, const int* in_sizes, int n_in,
                              void* d_out, int out_size) {
    const float* enc    = (const float*)d_in[0];
    const float* mems   = (const float*)d_in[1];
    const float* emb    = (const float*)d_in[2];
    const float* u      = (const float*)d_in[3];
    const float* vpar   = (const float*)d_in[4];
    const float* saWq   = (const float*)d_in[5];
    const float* saWk   = (const float*)d_in[6];
    const float* saWv   = (const float*)d_in[7];
    const float* saWr   = (const float*)d_in[8];
    const float* safcW  = (const float*)d_in[9];
    const float* safcB  = (const float*)d_in[10];
    const float* ln1g   = (const float*)d_in[11];
    const float* ln1b   = (const float*)d_in[12];
    const float* caWq   = (const float*)d_in[13];
    const float* caWk   = (const float*)d_in[14];
    const float* caWv   = (const float*)d_in[15];
    const float* cafcW  = (const float*)d_in[16];
    const float* cafcB  = (const float*)d_in[17];
    const float* ln2g   = (const float*)d_in[18];
    const float* ln2b   = (const float*)d_in[19];
    const float* ffW1   = (const float*)d_in[20];
    const float* ffb1   = (const float*)d_in[21];
    const float* ffW2   = (const float*)d_in[22];
    const float* ffb2   = (const float*)d_in[23];
    const float* ln3g   = (const float*)d_in[24];
    const float* ln3b   = (const float*)d_in[25];
    const float* outW   = (const float*)d_in[26];
    const int*   ids    = (const int*)  d_in[27];
    float* out = (float*)d_out;

    float *x, *tmp, *bdb;
    __half *hxh, *hmem, *hkv, *hcakv, *hr4, *hatt, *hq, *hff, *hremb, *henc;
    __half *wqkvh, *wcakvh, *wr4h, *wsafch, *wcafch, *wcaqh, *wff1h, *wff2h, *wouth;
    cudaGetSymbolAddress((void**)&x,      g_x);
    cudaGetSymbolAddress((void**)&tmp,    g_tmp);
    cudaGetSymbolAddress((void**)&bdb,    g_bd);
    cudaGetSymbolAddress((void**)&hxh,    g_hxh);
    cudaGetSymbolAddress((void**)&hmem,   g_hmem);
    cudaGetSymbolAddress((void**)&hkv,    g_hkv);
    cudaGetSymbolAddress((void**)&hcakv,  g_hcakv);
    cudaGetSymbolAddress((void**)&hr4,    g_hr4);
    cudaGetSymbolAddress((void**)&hatt,   g_hatt);
    cudaGetSymbolAddress((void**)&hq,     g_hq);
    cudaGetSymbolAddress((void**)&hff,    g_hff);
    cudaGetSymbolAddress((void**)&hremb,  g_hremb);
    cudaGetSymbolAddress((void**)&henc,   g_henc);
    cudaGetSymbolAddress((void**)&wqkvh,  g_wqkv);
    cudaGetSymbolAddress((void**)&wcakvh, g_wcakv);
    cudaGetSymbolAddress((void**)&wr4h,   g_wr4);
    cudaGetSymbolAddress((void**)&wsafch, g_wsafc);
    cudaGetSymbolAddress((void**)&wcafch, g_wcafc);
    cudaGetSymbolAddress((void**)&wcaqh,  g_wcaq);
    cudaGetSymbolAddress((void**)&wff1h,  g_wff1);
    cudaGetSymbolAddress((void**)&wff2h,  g_wff2);
    cudaGetSymbolAddress((void**)&wouth,  g_wout);

    static int smem_set = 0;
    if (!smem_set) {
        cudaFuncSetAttribute(flashmma, cudaFuncAttributeMaxDynamicSharedMemorySize,
                             FLASH_SMEM);
        cudaFuncSetAttribute((mm_h<true , true >), cudaFuncAttributeMaxDynamicSharedMemorySize, MM_SMEM);
        cudaFuncSetAttribute((mm_h<false, true >), cudaFuncAttributeMaxDynamicSharedMemorySize, MM_SMEM);
        cudaFuncSetAttribute((mm_h<false, false>), cudaFuncAttributeMaxDynamicSharedMemorySize, MM_SMEM);
        smem_set = 1;
    }

    // batched DM x DM transposes (9 weight groups x 4 layers, one launch)
    {
        TB9 tb;
        tb.s[0]=saWq;  tb.d[0]=wqkvh;                   tb.dbs[0]=(size_t)3072*DM;
        tb.s[1]=saWk;  tb.d[1]=wqkvh + (size_t)1024*DM; tb.dbs[1]=(size_t)3072*DM;
        tb.s[2]=saWv;  tb.d[2]=wqkvh + (size_t)2048*DM; tb.dbs[2]=(size_t)3072*DM;
        tb.s[3]=caWk;  tb.d[3]=wcakvh;                  tb.dbs[3]=(size_t)2048*DM;
        tb.s[4]=caWv;  tb.d[4]=wcakvh + (size_t)1024*DM;tb.dbs[4]=(size_t)2048*DM;
        tb.s[5]=saWr;  tb.d[5]=wr4h;                    tb.dbs[5]=(size_t)DM*DM;
        tb.s[6]=safcW; tb.d[6]=wsafch;                  tb.dbs[6]=(size_t)DM*DM;
        tb.s[7]=cafcW; tb.d[7]=wcafch;                  tb.dbs[7]=(size_t)DM*DM;
        tb.s[8]=caWq;  tb.d[8]=wcaqh;                   tb.dbs[8]=(size_t)DM*DM;
        trans_half9<<<dim3(DM/32, DM/32, 36), dim3(32, 8)>>>(tb);
    }
    dim3 tb2(32, 8);
    trans_half<<<dim3(FFN/32, DM/32, LNUM), tb2>>>(ffW1, wff1h, DM, FFN, (size_t)DM*FFN, (size_t)DM*FFN);
    trans_half<<<dim3(DM/32, FFN/32, LNUM), tb2>>>(ffW2, wff2h, FFN, DM, (size_t)DM*FFN, (size_t)DM*FFN);
    trans_half<<<dim3(VN/32, DM/32, 1),     tb2>>>(outW, wouth, DM, VN, 0, 0);
    half_copy<<<((BN*EN*DM/4) + 255)/256, 256>>>(enc, henc, BN*EN*DM/4);

    embed_kernel<<<(BN*QN*DM + 255)/256, 256>>>(ids, emb, x, hxh);
    remb_kernel <<<(KLEN*DM + 255)/256, 256>>>(hremb);

    // layer-independent projections (fused across layers)
    run_gemm(hremb, wr4h,   nullptr, hr4,   KLEN,  DM, 4096, false, true);
    run_gemm(henc,  wcakvh, nullptr, hcakv, BN*EN, DM, 8192, false, true);

    dim3 flash_grid(QN/128, HN, BN);
    dim3 bd_grid(KLEN/64, QN/128, BN*HN);

    for (int l = 0; l < LNUM; l++) {
        // ---- self-attention (TransformerXL relative) ----
        concat_kernel<<<(BN*KLEN*DM + 255)/256, 256>>>(
            mems + (size_t)l*BN*MN*DM, x, hmem);

        // Q on x rows only; K|V on full memb (saves 1/6 of old fused QKV)
        run_gemm(hxh,  wqkvh + (size_t)l*3072*DM, nullptr, hq,
                 BN*QN, DM, 1024, false, true);
        run_gemm(hmem, wqkvh + (size_t)l*3072*DM + (size_t)1024*DM, nullptr, hkv,
                 BN*KLEN, DM, 2048, false, true);

        bd_mma<<<bd_grid, 256>>>(hq, DM, (size_t)QN*DM,
                                 hr4 + (size_t)l*1024, 4096, vpar, bdb);
        flashmma<<<flash_grid, 256, FLASH_SMEM>>>(
            hq, DM, (size_t)QN*DM,
            hkv, hkv + 1024, 2048, (size_t)KLEN*2048,
            bdb, u, hatt, KLEN, 1);

        run_gemm(hatt, wsafch + (size_t)l*DM*DM, safcB + (size_t)l*DM,
                 tmp, BN*QN, DM, DM, false, false);
        ln_kernel<<<BN*QN, 256>>>(x, hxh, tmp, ln1g + (size_t)l*DM, ln1b + (size_t)l*DM);

        // ---- cross-attention ----
        run_gemm(hxh, wcaqh + (size_t)l*DM*DM, nullptr, hq, BN*QN, DM, DM, false, true);

        flashmma<<<flash_grid, 256, FLASH_SMEM>>>(
            hq, DM, (size_t)QN*DM,
            hcakv + (size_t)l*2048, hcakv + (size_t)l*2048 + 1024,
            8192, (size_t)EN*8192,
            nullptr, nullptr, hatt, EN, 0);

        run_gemm(hatt, wcafch + (size_t)l*DM*DM, cafcB + (size_t)l*DM,
                 tmp, BN*QN, DM, DM, false, false);
        ln_kernel<<<BN*QN, 256>>>(x, hxh, tmp, ln2g + (size_t)l*DM, ln2b + (size_t)l*DM);

        // ---- feed-forward ----
        run_gemm(hxh, wff1h + (size_t)l*DM*FFN, ffb1 + (size_t)l*FFN,
                 hff, BN*QN, DM, FFN, true, true);
        run_gemm(hff, wff2h + (size_t)l*DM*FFN, ffb2 + (size_t)l*DM,
                 tmp, BN*QN, FFN, DM, false, false);
        ln_kernel<<<BN*QN, 256>>>(x, hxh, tmp, ln3g + (size_t)l*DM, ln3b + (size_t)l*DM);
    }

    // ---- output projection ----
    run_gemm(hxh, wouth, nullptr, out, BN*QN, DM, VN, false, false);
}